// round 2
// baseline (speedup 1.0000x reference)
#include <cuda_runtime.h>
#include <math.h>

#define BB 2
#define TT 2048
#define CC 1024
#define HH 16
#define DD 64
#define C3 3072

// Scratch (allocation-free rule: __device__ globals)
__device__ float g_qkv[BB * TT * C3];  // [B,T,3C]  48 MB
__device__ float g_y[BB * TT * CC];    // [B,T,C]   16 MB

// ---------------------------------------------------------------------------
// SIMT fp32 GEMM: C[M,N] = A[M,K] @ B[K,N], row-major.
// BM=BN=128, BK=8, 256 threads, 8x8 microtile per thread.
// Per kk: 4x LDS.128 feed 64 FFMA  -> FMA-bound, not shared-bound.
// ---------------------------------------------------------------------------
__device__ __forceinline__ void gemm_body(const float* __restrict__ A,
                                          const float* __restrict__ Bm,
                                          float* __restrict__ Cm,
                                          int N, int K) {
    __shared__ float As[8][128];   // [k][m]
    __shared__ float Bs[8][128];   // [k][n]

    const int tid = threadIdx.x;
    const int tx = tid & 15;       // 0..15 -> n microtile
    const int ty = tid >> 4;       // 0..15 -> m microtile
    const int m0 = blockIdx.y * 128;
    const int n0 = blockIdx.x * 128;

    const int a_row  = tid >> 1;          // 0..127
    const int a_k4   = (tid & 1) << 2;    // 0 or 4
    const int b_krow = tid >> 5;          // 0..7
    const int b_n4   = (tid & 31) << 2;   // 0..124

    float acc[8][8];
#pragma unroll
    for (int i = 0; i < 8; i++)
#pragma unroll
        for (int j = 0; j < 8; j++) acc[i][j] = 0.f;

    const float* aptr = A + (size_t)(m0 + a_row) * K + a_k4;
    const float* bptr = Bm + (size_t)b_krow * N + n0 + b_n4;

    for (int k0 = 0; k0 < K; k0 += 8) {
        float4 av = *(const float4*)(aptr + k0);
        float4 bv = *(const float4*)(bptr + (size_t)k0 * N);
        As[a_k4 + 0][a_row] = av.x;
        As[a_k4 + 1][a_row] = av.y;
        As[a_k4 + 2][a_row] = av.z;
        As[a_k4 + 3][a_row] = av.w;
        *(float4*)&Bs[b_krow][b_n4] = bv;
        __syncthreads();

#pragma unroll
        for (int kk = 0; kk < 8; kk++) {
            float4 a0 = *(const float4*)&As[kk][ty * 8];
            float4 a1 = *(const float4*)&As[kk][ty * 8 + 4];
            float4 b0 = *(const float4*)&Bs[kk][tx * 8];
            float4 b1 = *(const float4*)&Bs[kk][tx * 8 + 4];
            float ar[8] = {a0.x, a0.y, a0.z, a0.w, a1.x, a1.y, a1.z, a1.w};
            float br[8] = {b0.x, b0.y, b0.z, b0.w, b1.x, b1.y, b1.z, b1.w};
#pragma unroll
            for (int i = 0; i < 8; i++)
#pragma unroll
                for (int j = 0; j < 8; j++)
                    acc[i][j] += ar[i] * br[j];
        }
        __syncthreads();
    }

#pragma unroll
    for (int i = 0; i < 8; i++) {
        float* crow = Cm + (size_t)(m0 + ty * 8 + i) * N + n0 + tx * 8;
        *(float4*)crow       = make_float4(acc[i][0], acc[i][1], acc[i][2], acc[i][3]);
        *(float4*)(crow + 4) = make_float4(acc[i][4], acc[i][5], acc[i][6], acc[i][7]);
    }
}

__global__ __launch_bounds__(256) void gemm_qkv_kernel(const float* __restrict__ x,
                                                       const float* __restrict__ w) {
    gemm_body(x, w, g_qkv, C3, CC);
}

__global__ __launch_bounds__(256) void gemm_proj_kernel(const float* __restrict__ w,
                                                        float* __restrict__ out) {
    gemm_body(g_y, w, out, CC, CC);
}

// ---------------------------------------------------------------------------
// Flash-style attention. One CTA per (b,h, 64-query tile). 256 threads.
// Thread (r = tid/4, cg = tid%4): owns query row r; computes S for the 16 keys
// j = cg + 4*jj (strided -> conflict-free K reads), owns O columns
// [cg*16, cg*16+16). Q row lives in registers. K and V share one smem buffer.
// Online softmax; per-row (m,l) replicated across the 4 threads of a row via
// shuffles (lanes r*4+cg are contiguous, xor 1/2 stays in the group).
// ---------------------------------------------------------------------------
__global__ __launch_bounds__(256) void attn_kernel() {
    __shared__ float KVs[64][68];  // K tile then V tile (stride 68: conflict-free)
    __shared__ float Ps[64][68];   // softmax probabilities for current tile

    const int tid = threadIdx.x;
    const int r  = tid >> 2;       // 0..63 query row in tile
    const int cg = tid & 3;        // 0..3 column group
    const int qt = blockIdx.x;     // 0..31 query tile
    const int b  = blockIdx.y >> 4;
    const int h  = blockIdx.y & 15;
    const int qrow = qt * 64 + r;

    // Q row -> registers (64 floats)
    const float* qptr = g_qkv + (size_t)(b * TT + qrow) * C3 + h * DD;
    float4 q[16];
#pragma unroll
    for (int i = 0; i < 16; i++) q[i] = *(const float4*)(qptr + 4 * i);

    float4 o[4];
#pragma unroll
    for (int i = 0; i < 4; i++) o[i] = make_float4(0.f, 0.f, 0.f, 0.f);
    float mrow = -1e30f, lrow = 0.f;

    const int kbase = b * TT;

    for (int kt = 0; kt < TT / 64; kt++) {
        // ---- load K tile [64 x 64] ----
#pragma unroll
        for (int i = 0; i < 4; i++) {
            int f = tid + 256 * i;
            int row = f >> 4, dq = f & 15;
            *(float4*)&KVs[row][dq * 4] =
                *(const float4*)(g_qkv + (size_t)(kbase + kt * 64 + row) * C3 + CC + h * DD + dq * 4);
        }
        __syncthreads();

        // ---- S = Q K^T * scale for 16 strided keys ----
        float p[16];
        float mloc = -1e30f;
#pragma unroll
        for (int jj = 0; jj < 16; jj++) {
            const int j = cg + 4 * jj;
            float s = 0.f;
#pragma unroll
            for (int dv = 0; dv < 16; dv++) {
                float4 kv = *(const float4*)&KVs[j][dv * 4];
                s += q[dv].x * kv.x;
                s += q[dv].y * kv.y;
                s += q[dv].z * kv.z;
                s += q[dv].w * kv.w;
            }
            s *= 0.125f;  // 1/sqrt(64)
            p[jj] = s;
            mloc = fmaxf(mloc, s);
        }
        // row max / sum across the 4 threads of this row
        mloc = fmaxf(mloc, __shfl_xor_sync(0xffffffffu, mloc, 1));
        mloc = fmaxf(mloc, __shfl_xor_sync(0xffffffffu, mloc, 2));
        const float mnew  = fmaxf(mrow, mloc);
        const float alpha = __expf(mrow - mnew);
        float lsum = 0.f;
#pragma unroll
        for (int jj = 0; jj < 16; jj++) {
            float pv = __expf(p[jj] - mnew);
            p[jj] = pv;
            lsum += pv;
        }
        lsum += __shfl_xor_sync(0xffffffffu, lsum, 1);
        lsum += __shfl_xor_sync(0xffffffffu, lsum, 2);
        lrow = lrow * alpha + lsum;
        mrow = mnew;

#pragma unroll
        for (int jj = 0; jj < 16; jj++) Ps[r][cg + 4 * jj] = p[jj];
        __syncthreads();  // P visible; all K reads done -> safe to overwrite KVs

        // ---- load V tile into the same buffer ----
#pragma unroll
        for (int i = 0; i < 4; i++) {
            int f = tid + 256 * i;
            int row = f >> 4, dq = f & 15;
            *(float4*)&KVs[row][dq * 4] =
                *(const float4*)(g_qkv + (size_t)(kbase + kt * 64 + row) * C3 + 2 * CC + h * DD + dq * 4);
        }
        __syncthreads();

        // ---- O = O*alpha + P @ V ----
#pragma unroll
        for (int i = 0; i < 4; i++) {
            o[i].x *= alpha; o[i].y *= alpha; o[i].z *= alpha; o[i].w *= alpha;
        }
#pragma unroll 4
        for (int j = 0; j < 64; j++) {
            const float pv = Ps[r][j];
#pragma unroll
            for (int i = 0; i < 4; i++) {
                float4 vv = *(const float4*)&KVs[j][cg * 16 + 4 * i];
                o[i].x += pv * vv.x;
                o[i].y += pv * vv.y;
                o[i].z += pv * vv.z;
                o[i].w += pv * vv.w;
            }
        }
        __syncthreads();  // V reads done before next K load
    }

    const float inv = 1.f / lrow;
    float* yp = g_y + (size_t)(b * TT + qrow) * CC + h * DD + cg * 16;
#pragma unroll
    for (int i = 0; i < 4; i++) {
        float4 ov = o[i];
        ov.x *= inv; ov.y *= inv; ov.z *= inv; ov.w *= inv;
        *(float4*)(yp + 4 * i) = ov;
    }
}

// ---------------------------------------------------------------------------
extern "C" void kernel_launch(void* const* d_in, const int* in_sizes, int n_in,
                              void* d_out, int out_size) {
    const float* x      = (const float*)d_in[0];   // [B,T,C]
    const float* w_attn = (const float*)d_in[1];   // [C,3C]
    const float* w_proj = (const float*)d_in[2];   // [C,C]
    float* out = (float*)d_out;                    // [B,T,C]

    gemm_qkv_kernel<<<dim3(C3 / 128, (BB * TT) / 128), 256>>>(x, w_attn);
    attn_kernel<<<dim3(TT / 64, BB * HH), 256>>>();
    gemm_proj_kernel<<<dim3(CC / 128, (BB * TT) / 128), 256>>>(w_proj, out);
}

// round 4
// speedup vs baseline: 3.8938x; 3.8938x over previous
#include <cuda_runtime.h>
#include <cuda_bf16.h>
#include <cstdint>

#define BB 2
#define TT 2048
#define CC 1024
#define HH 16
#define DD 64
#define C3 3072
#define MROWS 4096   // BB*TT
#define NBH 32       // BB*HH

// ---------------- device global scratch (allocation-free rule) ----------------
__device__ __align__(16) __nv_bfloat16 g_xh[MROWS * CC], g_xl[MROWS * CC];
__device__ __align__(16) __nv_bfloat16 g_wah[C3 * CC], g_wal[C3 * CC];     // w_attn^T (q cols pre-scaled)
__device__ __align__(16) __nv_bfloat16 g_wph[CC * CC], g_wpl[CC * CC];     // w_proj^T
__device__ __align__(16) __nv_bfloat16 g_qkvh[(size_t)MROWS * C3], g_qkvl[(size_t)MROWS * C3];
__device__ __align__(16) __nv_bfloat16 g_vth[NBH * DD * TT], g_vtl[NBH * DD * TT];  // V^T per head [d][t]
__device__ __align__(16) __nv_bfloat16 g_sh[(size_t)NBH * TT * TT];        // S then P (hi)
__device__ __align__(16) __nv_bfloat16 g_sl[(size_t)NBH * TT * TT];        // S then P (lo)
__device__ __align__(16) __nv_bfloat16 g_yh[MROWS * CC], g_yl[MROWS * CC]; // attn out [b,t,h*d]

// ---------------- helpers ----------------
__device__ __forceinline__ uint32_t smem_u32(const void* p) {
    uint32_t a;
    asm("{ .reg .u64 t; cvta.to.shared.u64 t, %1; cvt.u32.u64 %0, t; }" : "=r"(a) : "l"(p));
    return a;
}
__device__ __forceinline__ void cp16(uint32_t s, const void* g) {
    asm volatile("cp.async.cg.shared.global [%0], [%1], 16;" :: "r"(s), "l"(g));
}
__device__ __forceinline__ void ldm_x4(uint32_t addr, uint32_t* r) {
    asm volatile("ldmatrix.sync.aligned.m8n8.x4.shared.b16 {%0,%1,%2,%3}, [%4];"
                 : "=r"(r[0]), "=r"(r[1]), "=r"(r[2]), "=r"(r[3]) : "r"(addr));
}
__device__ __forceinline__ void mma16816(float* c, const uint32_t* a, const uint32_t* b) {
    asm volatile("mma.sync.aligned.m16n8k16.row.col.f32.bf16.bf16.f32 "
                 "{%0,%1,%2,%3}, {%4,%5,%6,%7}, {%8,%9}, {%0,%1,%2,%3};"
                 : "+f"(c[0]), "+f"(c[1]), "+f"(c[2]), "+f"(c[3])
                 : "r"(a[0]), "r"(a[1]), "r"(a[2]), "r"(a[3]), "r"(b[0]), "r"(b[1]));
}
__device__ __forceinline__ void bsplit(float v, __nv_bfloat16* h, __nv_bfloat16* l) {
    __nv_bfloat16 hh = __float2bfloat16(v);
    *h = hh;
    *l = __float2bfloat16(v - __bfloat162float(hh));
}
__device__ __forceinline__ void store_split(__nv_bfloat16* H, __nv_bfloat16* L,
                                            size_t idx, float x, float y) {
    __nv_bfloat162 h2, l2;
    bsplit(x, &h2.x, &l2.x);
    bsplit(y, &h2.y, &l2.y);
    *(__nv_bfloat162*)(H + idx) = h2;
    *(__nv_bfloat162*)(L + idx) = l2;
}

// ---------------- prep kernels ----------------
__global__ void __launch_bounds__(256) xprep_k(const float* __restrict__ x) {
    size_t i = ((size_t)blockIdx.x * 256 + threadIdx.x) * 4;
    float4 v = *(const float4*)(x + i);
    float vv[4] = {v.x, v.y, v.z, v.w};
    __nv_bfloat16 h[4], l[4];
#pragma unroll
    for (int e = 0; e < 4; e++) bsplit(vv[e], &h[e], &l[e]);
    *(uint2*)(g_xh + i) = *(uint2*)h;
    *(uint2*)(g_xl + i) = *(uint2*)l;
}

// transpose w [CC][N] -> wt [N][CC] with split; q-columns pre-scaled by 1/8
__global__ void __launch_bounds__(256) wprep_k(const float* __restrict__ w, int N, int isattn) {
    __shared__ float ts[32][33];
    int tx = threadIdx.x & 31, ty = threadIdx.x >> 5;
    int n0 = blockIdx.x * 32, c0 = blockIdx.y * 32;
#pragma unroll
    for (int j = 0; j < 4; j++)
        ts[ty + j * 8][tx] = w[(size_t)(c0 + ty + j * 8) * N + n0 + tx];
    __syncthreads();
    __nv_bfloat16* th = isattn ? g_wah : g_wph;
    __nv_bfloat16* tl = isattn ? g_wal : g_wpl;
#pragma unroll
    for (int j = 0; j < 4; j++) {
        int n = n0 + ty + j * 8;
        float v = ts[tx][ty + j * 8];
        if (isattn && n < CC) v *= 0.125f;  // fold 1/sqrt(D) into q (exact pow2)
        size_t a = (size_t)n * CC + c0 + tx;
        bsplit(v, &th[a], &tl[a]);
    }
}

// transpose per-head V from g_qkv (cols 2048..3071) into [bh][d][t]
__global__ void __launch_bounds__(256) vtrans_k() {
    __shared__ __nv_bfloat16 th[32][33], tl[32][33];
    int tx = threadIdx.x & 31, ty = threadIdx.x >> 5;
    int t0 = blockIdx.x * 32, d0 = blockIdx.y * 32, bh = blockIdx.z;
    int b = bh >> 4, h = bh & 15;
    size_t inb = ((size_t)b * TT) * C3 + 2 * CC + h * DD;
#pragma unroll
    for (int j = 0; j < 4; j++) {
        int t = t0 + ty + j * 8;
        th[ty + j * 8][tx] = g_qkvh[inb + (size_t)t * C3 + d0 + tx];
        tl[ty + j * 8][tx] = g_qkvl[inb + (size_t)t * C3 + d0 + tx];
    }
    __syncthreads();
    size_t ob = (size_t)bh * DD * TT;
#pragma unroll
    for (int j = 0; j < 4; j++) {
        int d = d0 + ty + j * 8;
        g_vth[ob + (size_t)d * TT + t0 + tx] = th[tx][ty + j * 8];
        g_vtl[ob + (size_t)d * TT + t0 + tx] = tl[tx][ty + j * 8];
    }
}

// ---------------- softmax (in place: S hi/lo -> P hi/lo) ----------------
__global__ void __launch_bounds__(256) softmax_k() {
    const int w = threadIdx.x >> 5, lane = threadIdx.x & 31;
    const size_t row = (size_t)blockIdx.x * 8 + w;
    __nv_bfloat16* sh_ = g_sh + row * TT;
    __nv_bfloat16* sl_ = g_sl + row * TT;
    float f[64];
#pragma unroll
    for (int j = 0; j < 8; j++) {
        uint4 a = *(const uint4*)(sh_ + (size_t)j * 256 + lane * 8);
        uint4 bq = *(const uint4*)(sl_ + (size_t)j * 256 + lane * 8);
        const __nv_bfloat16* ha = (const __nv_bfloat16*)&a;
        const __nv_bfloat16* lb = (const __nv_bfloat16*)&bq;
#pragma unroll
        for (int e = 0; e < 8; e++)
            f[j * 8 + e] = __bfloat162float(ha[e]) + __bfloat162float(lb[e]);
    }
    float m = f[0];
#pragma unroll
    for (int i = 1; i < 64; i++) m = fmaxf(m, f[i]);
#pragma unroll
    for (int o = 16; o; o >>= 1) m = fmaxf(m, __shfl_xor_sync(0xffffffffu, m, o));
    float s = 0.f;
#pragma unroll
    for (int i = 0; i < 64; i++) { f[i] = __expf(f[i] - m); s += f[i]; }
#pragma unroll
    for (int o = 16; o; o >>= 1) s += __shfl_xor_sync(0xffffffffu, s, o);
    const float inv = 1.f / s;
#pragma unroll
    for (int j = 0; j < 8; j++) {
        __nv_bfloat16 hb[8], lb2[8];
#pragma unroll
        for (int e = 0; e < 8; e++) bsplit(f[j * 8 + e] * inv, &hb[e], &lb2[e]);
        *(uint4*)(sh_ + (size_t)j * 256 + lane * 8) = *(uint4*)hb;
        *(uint4*)(sl_ + (size_t)j * 256 + lane * 8) = *(uint4*)lb2;
    }
}

// ---------------- mma.sync GEMM: D[M,N] = A[m][k] * B[n][k]^T, bf16x3 split ----------------
// MODE 0: qkv (x * w_attn^T) -> g_qkv hi/lo       M=4096 N=3072 K=1024
// MODE 1: S   (q * k^T)      -> g_s hi/lo          M=N=2048 K=64, per bh
// MODE 2: PV  (P * Vt^T)     -> g_y hi/lo          M=2048 N=64 K=2048, per bh
// MODE 3: proj(y * w_proj^T) -> out fp32           M=4096 N=1024 K=1024
template<int MODE>
__global__ void __launch_bounds__(256) gemm_mma(float* __restrict__ outp) {
    constexpr int NTILE = (MODE == 2) ? 64 : 128;
    constexpr int NC  = (MODE == 0) ? 32 : (MODE == 1) ? 2 : (MODE == 2) ? 64 : 32;
    constexpr int LDA = (MODE == 1) ? C3 : (MODE == 2) ? TT : CC;
    constexpr int LDB = (MODE == 1) ? C3 : (MODE == 2) ? TT : CC;
    constexpr int WN  = NTILE / 2;    // warp N extent (warps: 4 x 2)
    constexpr int NN8 = WN / 8;
    constexpr int NJ  = WN / 16;
    constexpr int ASZ = 128 * 80;     // padded rows (80B) -> conflict-free ldmatrix
    constexpr int BSZ = NTILE * 80;
    constexpr int STG = 2 * ASZ + 2 * BSZ;

    extern __shared__ char sm[];
    const uint32_t smu = smem_u32(sm);
    const int tid = threadIdx.x, lane = tid & 31, wid = tid >> 5;
    const int wm = wid & 3, wn = wid >> 2;
    const int warpM = wm * 32, warpN = wn * WN;
    const int nt = blockIdx.x, mt = blockIdx.y, bh = blockIdx.z;
    const int m0 = mt * 128, n0 = nt * NTILE;
    const int b = bh >> 4, h = bh & 15;

    const __nv_bfloat16 *a_h, *a_l, *b_h, *b_l;
    if constexpr (MODE == 0) {
        a_h = g_xh + (size_t)m0 * CC;  a_l = g_xl + (size_t)m0 * CC;
        b_h = g_wah + (size_t)n0 * CC; b_l = g_wal + (size_t)n0 * CC;
    } else if constexpr (MODE == 1) {
        size_t qb = (size_t)b * TT * C3 + h * DD;
        a_h = g_qkvh + qb + (size_t)m0 * C3;      a_l = g_qkvl + qb + (size_t)m0 * C3;
        b_h = g_qkvh + qb + CC + (size_t)n0 * C3; b_l = g_qkvl + qb + CC + (size_t)n0 * C3;
    } else if constexpr (MODE == 2) {
        size_t sb = (size_t)bh * TT * TT;
        a_h = g_sh + sb + (size_t)m0 * TT;  a_l = g_sl + sb + (size_t)m0 * TT;
        size_t vb = (size_t)bh * DD * TT;
        b_h = g_vth + vb;                   b_l = g_vtl + vb;
    } else {
        a_h = g_yh + (size_t)m0 * CC;  a_l = g_yl + (size_t)m0 * CC;
        b_h = g_wph + (size_t)n0 * CC; b_l = g_wpl + (size_t)n0 * CC;
    }

    auto load_stage = [&](int st, int kc) {
        const uint32_t s0 = smu + st * STG;
        const int k0 = kc * 32;
#pragma unroll
        for (int i0 = 0; i0 < 128 * 4; i0 += 256) {
            int i = i0 + tid, r = i >> 2, c = i & 3;
            uint32_t sa = s0 + r * 80 + c * 16;
            cp16(sa,       (const char*)(a_h + (size_t)r * LDA + k0) + c * 16);
            cp16(sa + ASZ, (const char*)(a_l + (size_t)r * LDA + k0) + c * 16);
        }
#pragma unroll
        for (int i0 = 0; i0 < NTILE * 4; i0 += 256) {
            int i = i0 + tid, r = i >> 2, c = i & 3;
            uint32_t sb2 = s0 + 2 * ASZ + r * 80 + c * 16;
            cp16(sb2,       (const char*)(b_h + (size_t)r * LDB + k0) + c * 16);
            cp16(sb2 + BSZ, (const char*)(b_l + (size_t)r * LDB + k0) + c * 16);
        }
        asm volatile("cp.async.commit_group;" ::: "memory");
    };

    // per-lane ldmatrix address offsets
    const int grp = lane >> 3, r8 = lane & 7;
    const uint32_t aOff = (uint32_t)((warpM + r8 + (grp & 1) * 8) * 80 + (grp >> 1) * 16);
    const uint32_t bOff = (uint32_t)((warpN + r8 + (grp >> 1) * 8) * 80 + (grp & 1) * 16);

    float acc[2][NN8][4];
#pragma unroll
    for (int mi = 0; mi < 2; mi++)
#pragma unroll
        for (int ni = 0; ni < NN8; ni++)
#pragma unroll
            for (int e = 0; e < 4; e++) acc[mi][ni][e] = 0.f;

    load_stage(0, 0);

    for (int c = 0; c < NC; c++) {
        if (c + 1 < NC) {
            load_stage((c + 1) & 1, c + 1);
            asm volatile("cp.async.wait_group 1;" ::: "memory");
        } else {
            asm volatile("cp.async.wait_group 0;" ::: "memory");
        }
        __syncthreads();

        const uint32_t sA = smu + (c & 1) * STG;
        const uint32_t sB = sA + 2 * ASZ;
#pragma unroll
        for (int kk = 0; kk < 2; kk++) {
            const uint32_t kb = kk * 32;
            uint32_t aFh[2][4], aFl[2][4], bF[NJ][4];
            ldm_x4(sA + aOff + kb,            aFh[0]);
            ldm_x4(sA + aOff + 16 * 80 + kb,  aFh[1]);
            ldm_x4(sA + ASZ + aOff + kb,           aFl[0]);
            ldm_x4(sA + ASZ + aOff + 16 * 80 + kb, aFl[1]);
#pragma unroll
            for (int nj = 0; nj < NJ; nj++)
                ldm_x4(sB + bOff + nj * 16 * 80 + kb, bF[nj]);
            // pass hh
#pragma unroll
            for (int mi = 0; mi < 2; mi++)
#pragma unroll
                for (int ni = 0; ni < NN8; ni++)
                    mma16816(acc[mi][ni], aFh[mi], &bF[ni >> 1][(ni & 1) * 2]);
            // pass lh
#pragma unroll
            for (int mi = 0; mi < 2; mi++)
#pragma unroll
                for (int ni = 0; ni < NN8; ni++)
                    mma16816(acc[mi][ni], aFl[mi], &bF[ni >> 1][(ni & 1) * 2]);
            // load B lo, pass hl
#pragma unroll
            for (int nj = 0; nj < NJ; nj++)
                ldm_x4(sB + BSZ + bOff + nj * 16 * 80 + kb, bF[nj]);
#pragma unroll
            for (int mi = 0; mi < 2; mi++)
#pragma unroll
                for (int ni = 0; ni < NN8; ni++)
                    mma16816(acc[mi][ni], aFh[mi], &bF[ni >> 1][(ni & 1) * 2]);
        }
        __syncthreads();
    }

    // ---------------- epilogue ----------------
    const int row_l = lane >> 2, col_l = (lane & 3) * 2;
#pragma unroll
    for (int mi = 0; mi < 2; mi++) {
#pragma unroll
        for (int ni = 0; ni < NN8; ni++) {
            const int gr0 = m0 + warpM + mi * 16 + row_l;
            const int gc  = n0 + warpN + ni * 8 + col_l;
            const float* cc = acc[mi][ni];
            if constexpr (MODE == 0) {
                store_split(g_qkvh, g_qkvl, (size_t)gr0 * C3 + gc,       cc[0], cc[1]);
                store_split(g_qkvh, g_qkvl, (size_t)(gr0 + 8) * C3 + gc, cc[2], cc[3]);
            } else if constexpr (MODE == 1) {
                const size_t zb = (size_t)bh * TT * TT;
                store_split(g_sh, g_sl, zb + (size_t)gr0 * TT + gc,       cc[0], cc[1]);
                store_split(g_sh, g_sl, zb + (size_t)(gr0 + 8) * TT + gc, cc[2], cc[3]);
            } else if constexpr (MODE == 2) {
                const size_t yb = ((size_t)b * TT) * CC + h * DD;
                store_split(g_yh, g_yl, yb + (size_t)gr0 * CC + gc,       cc[0], cc[1]);
                store_split(g_yh, g_yl, yb + (size_t)(gr0 + 8) * CC + gc, cc[2], cc[3]);
            } else {
                *(float2*)(outp + (size_t)gr0 * CC + gc)       = make_float2(cc[0], cc[1]);
                *(float2*)(outp + (size_t)(gr0 + 8) * CC + gc) = make_float2(cc[2], cc[3]);
            }
        }
    }
}

// ---------------- host launcher ----------------
extern "C" void kernel_launch(void* const* d_in, const int* in_sizes, int n_in,
                              void* d_out, int out_size) {
    const float* x  = (const float*)d_in[0];
    const float* wa = (const float*)d_in[1];
    const float* wp = (const float*)d_in[2];
    float* out = (float*)d_out;

    constexpr int SM_BIG = 2 * (2 * 128 * 80 + 2 * 128 * 80);  // 81920
    constexpr int SM_PV  = 2 * (2 * 128 * 80 + 2 * 64 * 80);   // 61440

    cudaFuncSetAttribute((const void*)gemm_mma<0>, cudaFuncAttributeMaxDynamicSharedMemorySize, SM_BIG);
    cudaFuncSetAttribute((const void*)gemm_mma<1>, cudaFuncAttributeMaxDynamicSharedMemorySize, SM_BIG);
    cudaFuncSetAttribute((const void*)gemm_mma<2>, cudaFuncAttributeMaxDynamicSharedMemorySize, SM_PV);
    cudaFuncSetAttribute((const void*)gemm_mma<3>, cudaFuncAttributeMaxDynamicSharedMemorySize, SM_BIG);

    xprep_k<<<MROWS * CC / 1024, 256>>>(x);
    wprep_k<<<dim3(C3 / 32, CC / 32), 256>>>(wa, C3, 1);
    wprep_k<<<dim3(CC / 32, CC / 32), 256>>>(wp, CC, 0);

    gemm_mma<0><<<dim3(C3 / 128, MROWS / 128, 1), 256, SM_BIG>>>(nullptr);  // qkv
    vtrans_k<<<dim3(TT / 32, DD / 32, NBH), 256>>>();                       // V -> [bh][d][t]
    gemm_mma<1><<<dim3(TT / 128, TT / 128, NBH), 256, SM_BIG>>>(nullptr);   // S = q k^T
    softmax_k<<<NBH * TT / 8, 256>>>();                                     // S -> P
    gemm_mma<2><<<dim3(1, TT / 128, NBH), 256, SM_PV>>>(nullptr);           // y = P V
    gemm_mma<3><<<dim3(CC / 128, MROWS / 128, 1), 256, SM_BIG>>>(out);      // proj
}

// round 5
// speedup vs baseline: 5.0770x; 1.3039x over previous
#include <cuda_runtime.h>
#include <cuda_bf16.h>
#include <cstdint>

#define BB 2
#define TT 2048
#define CC 1024
#define HH 16
#define DD 64
#define C3 3072
#define MROWS 4096   // BB*TT
#define NBH 32       // BB*HH

// ---------------- device global scratch ----------------
__device__ __align__(16) __nv_bfloat16 g_xh[MROWS * CC], g_xl[MROWS * CC];
__device__ __align__(16) __nv_bfloat16 g_wah[C3 * CC], g_wal[C3 * CC];     // w_attn^T (q cols pre-scaled)
__device__ __align__(16) __nv_bfloat16 g_wph[CC * CC], g_wpl[CC * CC];     // w_proj^T
__device__ __align__(16) __nv_bfloat16 g_qkvh[(size_t)MROWS * C3], g_qkvl[(size_t)MROWS * C3];
__device__ __align__(16) __nv_bfloat16 g_yh[MROWS * CC], g_yl[MROWS * CC]; // attn out [b,t,h*d]

// ---------------- helpers ----------------
__device__ __forceinline__ uint32_t smem_u32(const void* p) {
    uint32_t a;
    asm("{ .reg .u64 t; cvta.to.shared.u64 t, %1; cvt.u32.u64 %0, t; }" : "=r"(a) : "l"(p));
    return a;
}
__device__ __forceinline__ void cp16(uint32_t s, const void* g) {
    asm volatile("cp.async.cg.shared.global [%0], [%1], 16;" :: "r"(s), "l"(g));
}
__device__ __forceinline__ void ldm_x4(uint32_t addr, uint32_t* r) {
    asm volatile("ldmatrix.sync.aligned.m8n8.x4.shared.b16 {%0,%1,%2,%3}, [%4];"
                 : "=r"(r[0]), "=r"(r[1]), "=r"(r[2]), "=r"(r[3]) : "r"(addr));
}
__device__ __forceinline__ void ldm_x4t(uint32_t addr, uint32_t* r) {
    asm volatile("ldmatrix.sync.aligned.m8n8.x4.trans.shared.b16 {%0,%1,%2,%3}, [%4];"
                 : "=r"(r[0]), "=r"(r[1]), "=r"(r[2]), "=r"(r[3]) : "r"(addr));
}
__device__ __forceinline__ void mma16816(float* c, const uint32_t* a, const uint32_t* b) {
    asm volatile("mma.sync.aligned.m16n8k16.row.col.f32.bf16.bf16.f32 "
                 "{%0,%1,%2,%3}, {%4,%5,%6,%7}, {%8,%9}, {%0,%1,%2,%3};"
                 : "+f"(c[0]), "+f"(c[1]), "+f"(c[2]), "+f"(c[3])
                 : "r"(a[0]), "r"(a[1]), "r"(a[2]), "r"(a[3]), "r"(b[0]), "r"(b[1]));
}
__device__ __forceinline__ void bsplit(float v, __nv_bfloat16* h, __nv_bfloat16* l) {
    __nv_bfloat16 hh = __float2bfloat16(v);
    *h = hh;
    *l = __float2bfloat16(v - __bfloat162float(hh));
}
__device__ __forceinline__ void store_split(__nv_bfloat16* H, __nv_bfloat16* L,
                                            size_t idx, float x, float y) {
    __nv_bfloat162 h2, l2;
    bsplit(x, &h2.x, &l2.x);
    bsplit(y, &h2.y, &l2.y);
    *(__nv_bfloat162*)(H + idx) = h2;
    *(__nv_bfloat162*)(L + idx) = l2;
}
// split two floats -> packed bf16x2 hi and lo words (low half = first value)
__device__ __forceinline__ void split2(float x, float y, uint32_t& hw, uint32_t& lw) {
    __nv_bfloat16 hx = __float2bfloat16(x), hy = __float2bfloat16(y);
    __nv_bfloat16 lx = __float2bfloat16(x - __bfloat162float(hx));
    __nv_bfloat16 ly = __float2bfloat16(y - __bfloat162float(hy));
    hw = (uint32_t)*(uint16_t*)&hx | ((uint32_t)*(uint16_t*)&hy << 16);
    lw = (uint32_t)*(uint16_t*)&lx | ((uint32_t)*(uint16_t*)&ly << 16);
}

// ---------------- prep kernels ----------------
__global__ void __launch_bounds__(256) xprep_k(const float* __restrict__ x) {
    size_t i = ((size_t)blockIdx.x * 256 + threadIdx.x) * 4;
    float4 v = *(const float4*)(x + i);
    float vv[4] = {v.x, v.y, v.z, v.w};
    __nv_bfloat16 h[4], l[4];
#pragma unroll
    for (int e = 0; e < 4; e++) bsplit(vv[e], &h[e], &l[e]);
    *(uint2*)(g_xh + i) = *(uint2*)h;
    *(uint2*)(g_xl + i) = *(uint2*)l;
}

__global__ void __launch_bounds__(256) wprep_k(const float* __restrict__ w, int N, int isattn) {
    __shared__ float ts[32][33];
    int tx = threadIdx.x & 31, ty = threadIdx.x >> 5;
    int n0 = blockIdx.x * 32, c0 = blockIdx.y * 32;
#pragma unroll
    for (int j = 0; j < 4; j++)
        ts[ty + j * 8][tx] = w[(size_t)(c0 + ty + j * 8) * N + n0 + tx];
    __syncthreads();
    __nv_bfloat16* th = isattn ? g_wah : g_wph;
    __nv_bfloat16* tl = isattn ? g_wal : g_wpl;
#pragma unroll
    for (int j = 0; j < 4; j++) {
        int n = n0 + ty + j * 8;
        float v = ts[tx][ty + j * 8];
        if (isattn && n < CC) v *= 0.125f;  // fold 1/sqrt(D) into q
        size_t a = (size_t)n * CC + c0 + tx;
        bsplit(v, &th[a], &tl[a]);
    }
}

// ---------------- mma.sync GEMM (qkv / proj) ----------------
// MODE 0: qkv (x * w_attn^T) -> g_qkv hi/lo   M=4096 N=3072 K=1024
// MODE 3: proj(y * w_proj^T) -> out fp32      M=4096 N=1024 K=1024
template<int MODE>
__global__ void __launch_bounds__(256) gemm_mma(float* __restrict__ outp) {
    constexpr int NTILE = 128;
    constexpr int NC  = 32;
    constexpr int LDA = CC, LDB = CC;
    constexpr int WN  = NTILE / 2;
    constexpr int NN8 = WN / 8;
    constexpr int NJ  = WN / 16;
    constexpr int ASZ = 128 * 80;
    constexpr int BSZ = NTILE * 80;
    constexpr int STG = 2 * ASZ + 2 * BSZ;

    extern __shared__ char sm[];
    const uint32_t smu = smem_u32(sm);
    const int tid = threadIdx.x, lane = tid & 31, wid = tid >> 5;
    const int wm = wid & 3, wn = wid >> 2;
    const int warpM = wm * 32, warpN = wn * WN;
    const int nt = blockIdx.x, mt = blockIdx.y;
    const int m0 = mt * 128, n0 = nt * NTILE;

    const __nv_bfloat16 *a_h, *a_l, *b_h, *b_l;
    if constexpr (MODE == 0) {
        a_h = g_xh + (size_t)m0 * CC;  a_l = g_xl + (size_t)m0 * CC;
        b_h = g_wah + (size_t)n0 * CC; b_l = g_wal + (size_t)n0 * CC;
    } else {
        a_h = g_yh + (size_t)m0 * CC;  a_l = g_yl + (size_t)m0 * CC;
        b_h = g_wph + (size_t)n0 * CC; b_l = g_wpl + (size_t)n0 * CC;
    }

    auto load_stage = [&](int st, int kc) {
        const uint32_t s0 = smu + st * STG;
        const int k0 = kc * 32;
#pragma unroll
        for (int i0 = 0; i0 < 128 * 4; i0 += 256) {
            int i = i0 + tid, r = i >> 2, c = i & 3;
            uint32_t sa = s0 + r * 80 + c * 16;
            cp16(sa,       (const char*)(a_h + (size_t)r * LDA + k0) + c * 16);
            cp16(sa + ASZ, (const char*)(a_l + (size_t)r * LDA + k0) + c * 16);
        }
#pragma unroll
        for (int i0 = 0; i0 < NTILE * 4; i0 += 256) {
            int i = i0 + tid, r = i >> 2, c = i & 3;
            uint32_t sb2 = s0 + 2 * ASZ + r * 80 + c * 16;
            cp16(sb2,       (const char*)(b_h + (size_t)r * LDB + k0) + c * 16);
            cp16(sb2 + BSZ, (const char*)(b_l + (size_t)r * LDB + k0) + c * 16);
        }
        asm volatile("cp.async.commit_group;" ::: "memory");
    };

    const int grp = lane >> 3, r8 = lane & 7;
    const uint32_t aOff = (uint32_t)((warpM + r8 + (grp & 1) * 8) * 80 + (grp >> 1) * 16);
    const uint32_t bOff = (uint32_t)((warpN + r8 + (grp >> 1) * 8) * 80 + (grp & 1) * 16);

    float acc[2][NN8][4];
#pragma unroll
    for (int mi = 0; mi < 2; mi++)
#pragma unroll
        for (int ni = 0; ni < NN8; ni++)
#pragma unroll
            for (int e = 0; e < 4; e++) acc[mi][ni][e] = 0.f;

    load_stage(0, 0);

    for (int c = 0; c < NC; c++) {
        if (c + 1 < NC) {
            load_stage((c + 1) & 1, c + 1);
            asm volatile("cp.async.wait_group 1;" ::: "memory");
        } else {
            asm volatile("cp.async.wait_group 0;" ::: "memory");
        }
        __syncthreads();

        const uint32_t sA = smu + (c & 1) * STG;
        const uint32_t sB = sA + 2 * ASZ;
#pragma unroll
        for (int kk = 0; kk < 2; kk++) {
            const uint32_t kb = kk * 32;
            uint32_t aFh[2][4], aFl[2][4], bF[NJ][4];
            ldm_x4(sA + aOff + kb,            aFh[0]);
            ldm_x4(sA + aOff + 16 * 80 + kb,  aFh[1]);
            ldm_x4(sA + ASZ + aOff + kb,           aFl[0]);
            ldm_x4(sA + ASZ + aOff + 16 * 80 + kb, aFl[1]);
#pragma unroll
            for (int nj = 0; nj < NJ; nj++)
                ldm_x4(sB + bOff + nj * 16 * 80 + kb, bF[nj]);
#pragma unroll
            for (int mi = 0; mi < 2; mi++)
#pragma unroll
                for (int ni = 0; ni < NN8; ni++)
                    mma16816(acc[mi][ni], aFh[mi], &bF[ni >> 1][(ni & 1) * 2]);
#pragma unroll
            for (int mi = 0; mi < 2; mi++)
#pragma unroll
                for (int ni = 0; ni < NN8; ni++)
                    mma16816(acc[mi][ni], aFl[mi], &bF[ni >> 1][(ni & 1) * 2]);
#pragma unroll
            for (int nj = 0; nj < NJ; nj++)
                ldm_x4(sB + BSZ + bOff + nj * 16 * 80 + kb, bF[nj]);
#pragma unroll
            for (int mi = 0; mi < 2; mi++)
#pragma unroll
                for (int ni = 0; ni < NN8; ni++)
                    mma16816(acc[mi][ni], aFh[mi], &bF[ni >> 1][(ni & 1) * 2]);
        }
        __syncthreads();
    }

    const int row_l = lane >> 2, col_l = (lane & 3) * 2;
#pragma unroll
    for (int mi = 0; mi < 2; mi++) {
#pragma unroll
        for (int ni = 0; ni < NN8; ni++) {
            const int gr0 = m0 + warpM + mi * 16 + row_l;
            const int gc  = n0 + warpN + ni * 8 + col_l;
            const float* cc = acc[mi][ni];
            if constexpr (MODE == 0) {
                store_split(g_qkvh, g_qkvl, (size_t)gr0 * C3 + gc,       cc[0], cc[1]);
                store_split(g_qkvh, g_qkvl, (size_t)(gr0 + 8) * C3 + gc, cc[2], cc[3]);
            } else {
                *(float2*)(outp + (size_t)gr0 * CC + gc)       = make_float2(cc[0], cc[1]);
                *(float2*)(outp + (size_t)(gr0 + 8) * CC + gc) = make_float2(cc[2], cc[3]);
            }
        }
    }
}

// ---------------- fused flash attention ----------------
// Grid (TT/128, NBH); 8 warps; warp handles 16 q rows x full 64 d.
// K/V 64-key tiles double-buffered in smem (144B padded rows).
// S = QK^T and PV both via 3-pass bf16-split mma; online softmax in registers.
__global__ void __launch_bounds__(256) flash_k() {
    constexpr int RSTR = 144;
    constexpr int BUF  = 64 * RSTR;   // one 64x64 bf16 tile buffer
    constexpr int STG  = 4 * BUF;     // Kh,Kl,Vh,Vl
    constexpr int NT   = TT / 64;     // 32 key tiles

    extern __shared__ char sm[];
    const uint32_t smu = smem_u32(sm);
    const int tid = threadIdx.x, lane = tid & 31, wid = tid >> 5;
    const int qt = blockIdx.x, bh = blockIdx.y;
    const int b = bh >> 4, h = bh & 15;
    const int r = lane >> 2, cq = (lane & 3) * 2;

    // Q fragments (hi/lo) loaded directly from global (reused all 32 tiles)
    const size_t qbase = ((size_t)b * TT + qt * 128 + wid * 16) * C3 + h * DD;
    uint32_t qfh[4][4], qfl[4][4];
#pragma unroll
    for (int kc = 0; kc < 4; kc++)
#pragma unroll
        for (int e = 0; e < 4; e++) {
            size_t off = qbase + (size_t)(r + (e & 1) * 8) * C3 + kc * 16 + cq + (e >> 1) * 8;
            qfh[kc][e] = *(const uint32_t*)(g_qkvh + off);
            qfl[kc][e] = *(const uint32_t*)(g_qkvl + off);
        }

    float oacc[8][4];
#pragma unroll
    for (int nf = 0; nf < 8; nf++)
#pragma unroll
        for (int e = 0; e < 4; e++) oacc[nf][e] = 0.f;
    float m0r = -1e30f, m1r = -1e30f, l0r = 0.f, l1r = 0.f;

    const int grp = lane >> 3, r8 = lane & 7;
    const uint32_t kOff = (uint32_t)((r8 + (grp >> 1) * 8) * RSTR + (grp & 1) * 16);
    const uint32_t vOff = (uint32_t)(((grp & 1) * 8 + r8) * RSTR + (grp >> 1) * 16);
    const size_t kvb = (size_t)b * TT * C3 + h * DD;

    auto load_tile = [&](int kt, int st) {
        const uint32_t s0 = smu + st * STG;
        const int t0 = kt * 64;
#pragma unroll
        for (int it = 0; it < 2; it++) {
            int i = it * 256 + tid;
            int rr = i >> 3, c = i & 7;
            const __nv_bfloat16* gk = g_qkvh + kvb + (size_t)(t0 + rr) * C3 + CC + c * 8;
            const __nv_bfloat16* gkl = g_qkvl + kvb + (size_t)(t0 + rr) * C3 + CC + c * 8;
            const __nv_bfloat16* gv = g_qkvh + kvb + (size_t)(t0 + rr) * C3 + 2 * CC + c * 8;
            const __nv_bfloat16* gvl = g_qkvl + kvb + (size_t)(t0 + rr) * C3 + 2 * CC + c * 8;
            uint32_t sa = s0 + rr * RSTR + c * 16;
            cp16(sa,           gk);
            cp16(sa + BUF,     gkl);
            cp16(sa + 2 * BUF, gv);
            cp16(sa + 3 * BUF, gvl);
        }
        asm volatile("cp.async.commit_group;" ::: "memory");
    };

    load_tile(0, 0);

    for (int kt = 0; kt < NT; kt++) {
        if (kt + 1 < NT) {
            load_tile(kt + 1, (kt + 1) & 1);
            asm volatile("cp.async.wait_group 1;" ::: "memory");
        } else {
            asm volatile("cp.async.wait_group 0;" ::: "memory");
        }
        __syncthreads();
        const uint32_t sK = smu + (kt & 1) * STG;
        const uint32_t sV = sK + 2 * BUF;

        // ---- S = Q K^T (3-pass split) ----
        float sacc[8][4];
#pragma unroll
        for (int nf = 0; nf < 8; nf++)
#pragma unroll
            for (int e = 0; e < 4; e++) sacc[nf][e] = 0.f;
#pragma unroll
        for (int kk = 0; kk < 4; kk++) {
            uint32_t bFh[4][4], bFl[4][4];
#pragma unroll
            for (int nj = 0; nj < 4; nj++)
                ldm_x4(sK + kOff + nj * 16 * RSTR + kk * 32, bFh[nj]);
#pragma unroll
            for (int nf = 0; nf < 8; nf++) {
                mma16816(sacc[nf], qfh[kk], &bFh[nf >> 1][(nf & 1) * 2]);
                mma16816(sacc[nf], qfl[kk], &bFh[nf >> 1][(nf & 1) * 2]);
            }
#pragma unroll
            for (int nj = 0; nj < 4; nj++)
                ldm_x4(sK + BUF + kOff + nj * 16 * RSTR + kk * 32, bFl[nj]);
#pragma unroll
            for (int nf = 0; nf < 8; nf++)
                mma16816(sacc[nf], qfh[kk], &bFl[nf >> 1][(nf & 1) * 2]);
        }

        // ---- online softmax ----
        float mx0 = -1e30f, mx1 = -1e30f;
#pragma unroll
        for (int nf = 0; nf < 8; nf++) {
            mx0 = fmaxf(mx0, fmaxf(sacc[nf][0], sacc[nf][1]));
            mx1 = fmaxf(mx1, fmaxf(sacc[nf][2], sacc[nf][3]));
        }
        mx0 = fmaxf(mx0, __shfl_xor_sync(0xffffffffu, mx0, 1));
        mx0 = fmaxf(mx0, __shfl_xor_sync(0xffffffffu, mx0, 2));
        mx1 = fmaxf(mx1, __shfl_xor_sync(0xffffffffu, mx1, 1));
        mx1 = fmaxf(mx1, __shfl_xor_sync(0xffffffffu, mx1, 2));
        const float mn0 = fmaxf(m0r, mx0), mn1 = fmaxf(m1r, mx1);
        const float al0 = __expf(m0r - mn0), al1 = __expf(m1r - mn1);
        float ls0 = 0.f, ls1 = 0.f;
#pragma unroll
        for (int nf = 0; nf < 8; nf++) {
            sacc[nf][0] = __expf(sacc[nf][0] - mn0);
            sacc[nf][1] = __expf(sacc[nf][1] - mn0);
            sacc[nf][2] = __expf(sacc[nf][2] - mn1);
            sacc[nf][3] = __expf(sacc[nf][3] - mn1);
            ls0 += sacc[nf][0] + sacc[nf][1];
            ls1 += sacc[nf][2] + sacc[nf][3];
        }
        ls0 += __shfl_xor_sync(0xffffffffu, ls0, 1);
        ls0 += __shfl_xor_sync(0xffffffffu, ls0, 2);
        ls1 += __shfl_xor_sync(0xffffffffu, ls1, 1);
        ls1 += __shfl_xor_sync(0xffffffffu, ls1, 2);
        l0r = l0r * al0 + ls0; m0r = mn0;
        l1r = l1r * al1 + ls1; m1r = mn1;
#pragma unroll
        for (int nf = 0; nf < 8; nf++) {
            oacc[nf][0] *= al0; oacc[nf][1] *= al0;
            oacc[nf][2] *= al1; oacc[nf][3] *= al1;
        }

        // ---- P -> bf16 hi/lo A-fragments (accumulator layout identity) ----
        uint32_t pfh[4][4], pfl[4][4];
#pragma unroll
        for (int kc = 0; kc < 4; kc++) {
            split2(sacc[2 * kc][0],     sacc[2 * kc][1],     pfh[kc][0], pfl[kc][0]);
            split2(sacc[2 * kc][2],     sacc[2 * kc][3],     pfh[kc][1], pfl[kc][1]);
            split2(sacc[2 * kc + 1][0], sacc[2 * kc + 1][1], pfh[kc][2], pfl[kc][2]);
            split2(sacc[2 * kc + 1][2], sacc[2 * kc + 1][3], pfh[kc][3], pfl[kc][3]);
        }

        // ---- O += P V (3-pass split), V via ldmatrix.trans ----
#pragma unroll
        for (int kc = 0; kc < 4; kc++) {
            uint32_t vFh[4][4], vFl[4][4];
#pragma unroll
            for (int db = 0; db < 4; db++)
                ldm_x4t(sV + kc * 16 * RSTR + vOff + db * 32, vFh[db]);
#pragma unroll
            for (int nf = 0; nf < 8; nf++) {
                mma16816(oacc[nf], pfh[kc], &vFh[nf >> 1][(nf & 1) * 2]);
                mma16816(oacc[nf], pfl[kc], &vFh[nf >> 1][(nf & 1) * 2]);
            }
#pragma unroll
            for (int db = 0; db < 4; db++)
                ldm_x4t(sV + BUF + kc * 16 * RSTR + vOff + db * 32, vFl[db]);
#pragma unroll
            for (int nf = 0; nf < 8; nf++)
                mma16816(oacc[nf], pfh[kc], &vFl[nf >> 1][(nf & 1) * 2]);
        }
        __syncthreads();
    }

    // ---- epilogue: normalize and write y split ----
    const float inv0 = 1.f / l0r, inv1 = 1.f / l1r;
    const size_t yb = ((size_t)b * TT + qt * 128 + wid * 16) * CC + h * DD;
#pragma unroll
    for (int nf = 0; nf < 8; nf++) {
        const int col = nf * 8 + cq;
        store_split(g_yh, g_yl, yb + (size_t)r * CC + col,
                    oacc[nf][0] * inv0, oacc[nf][1] * inv0);
        store_split(g_yh, g_yl, yb + (size_t)(r + 8) * CC + col,
                    oacc[nf][2] * inv1, oacc[nf][3] * inv1);
    }
}

// ---------------- host launcher ----------------
extern "C" void kernel_launch(void* const* d_in, const int* in_sizes, int n_in,
                              void* d_out, int out_size) {
    const float* x  = (const float*)d_in[0];
    const float* wa = (const float*)d_in[1];
    const float* wp = (const float*)d_in[2];
    float* out = (float*)d_out;

    constexpr int SM_GEMM  = 2 * (2 * 128 * 80 + 2 * 128 * 80);  // 81920
    constexpr int SM_FLASH = 2 * 4 * 64 * 144;                   // 73728

    cudaFuncSetAttribute((const void*)gemm_mma<0>, cudaFuncAttributeMaxDynamicSharedMemorySize, SM_GEMM);
    cudaFuncSetAttribute((const void*)gemm_mma<3>, cudaFuncAttributeMaxDynamicSharedMemorySize, SM_GEMM);
    cudaFuncSetAttribute((const void*)flash_k,     cudaFuncAttributeMaxDynamicSharedMemorySize, SM_FLASH);

    xprep_k<<<MROWS * CC / 1024, 256>>>(x);
    wprep_k<<<dim3(C3 / 32, CC / 32), 256>>>(wa, C3, 1);
    wprep_k<<<dim3(CC / 32, CC / 32), 256>>>(wp, CC, 0);

    gemm_mma<0><<<dim3(C3 / 128, MROWS / 128), 256, SM_GEMM>>>(nullptr);  // qkv
    flash_k<<<dim3(TT / 128, NBH), 256, SM_FLASH>>>();                    // fused attention
    gemm_mma<3><<<dim3(CC / 128, MROWS / 128), 256, SM_GEMM>>>(out);      // proj
}

// round 6
// speedup vs baseline: 5.1734x; 1.0190x over previous
#include <cuda_runtime.h>
#include <cuda_bf16.h>
#include <cstdint>

#define BB 2
#define TT 2048
#define CC 1024
#define HH 16
#define DD 64
#define C3 3072
#define MROWS 4096   // BB*TT
#define NBH 32       // BB*HH

// ---------------- device global scratch ----------------
__device__ __align__(16) __nv_bfloat16 g_xh[MROWS * CC], g_xl[MROWS * CC];
__device__ __align__(16) __nv_bfloat16 g_wah[C3 * CC], g_wal[C3 * CC];     // w_attn^T (q cols pre-scaled by 0.125*log2e)
__device__ __align__(16) __nv_bfloat16 g_wph[CC * CC], g_wpl[CC * CC];     // w_proj^T
__device__ __align__(16) __nv_bfloat16 g_qkvh[(size_t)MROWS * C3], g_qkvl[(size_t)MROWS * C3];
__device__ __align__(16) __nv_bfloat16 g_yh[MROWS * CC], g_yl[MROWS * CC]; // attn out [b,t,h*d]

// ---------------- helpers ----------------
__device__ __forceinline__ uint32_t smem_u32(const void* p) {
    uint32_t a;
    asm("{ .reg .u64 t; cvta.to.shared.u64 t, %1; cvt.u32.u64 %0, t; }" : "=r"(a) : "l"(p));
    return a;
}
__device__ __forceinline__ void cp16(uint32_t s, const void* g) {
    asm volatile("cp.async.cg.shared.global [%0], [%1], 16;" :: "r"(s), "l"(g));
}
__device__ __forceinline__ void ldm_x4(uint32_t addr, uint32_t* r) {
    asm volatile("ldmatrix.sync.aligned.m8n8.x4.shared.b16 {%0,%1,%2,%3}, [%4];"
                 : "=r"(r[0]), "=r"(r[1]), "=r"(r[2]), "=r"(r[3]) : "r"(addr));
}
__device__ __forceinline__ void ldm_x4t(uint32_t addr, uint32_t* r) {
    asm volatile("ldmatrix.sync.aligned.m8n8.x4.trans.shared.b16 {%0,%1,%2,%3}, [%4];"
                 : "=r"(r[0]), "=r"(r[1]), "=r"(r[2]), "=r"(r[3]) : "r"(addr));
}
__device__ __forceinline__ void mma16816(float* c, const uint32_t* a, const uint32_t* b) {
    asm volatile("mma.sync.aligned.m16n8k16.row.col.f32.bf16.bf16.f32 "
                 "{%0,%1,%2,%3}, {%4,%5,%6,%7}, {%8,%9}, {%0,%1,%2,%3};"
                 : "+f"(c[0]), "+f"(c[1]), "+f"(c[2]), "+f"(c[3])
                 : "r"(a[0]), "r"(a[1]), "r"(a[2]), "r"(a[3]), "r"(b[0]), "r"(b[1]));
}
__device__ __forceinline__ void bsplit(float v, __nv_bfloat16* h, __nv_bfloat16* l) {
    __nv_bfloat16 hh = __float2bfloat16(v);
    *h = hh;
    *l = __float2bfloat16(v - __bfloat162float(hh));
}
__device__ __forceinline__ void store_split(__nv_bfloat16* H, __nv_bfloat16* L,
                                            size_t idx, float x, float y) {
    __nv_bfloat162 h2, l2;
    bsplit(x, &h2.x, &l2.x);
    bsplit(y, &h2.y, &l2.y);
    *(__nv_bfloat162*)(H + idx) = h2;
    *(__nv_bfloat162*)(L + idx) = l2;
}
__device__ __forceinline__ void split2(float x, float y, uint32_t& hw, uint32_t& lw) {
    __nv_bfloat16 hx = __float2bfloat16(x), hy = __float2bfloat16(y);
    __nv_bfloat16 lx = __float2bfloat16(x - __bfloat162float(hx));
    __nv_bfloat16 ly = __float2bfloat16(y - __bfloat162float(hy));
    hw = (uint32_t)*(uint16_t*)&hx | ((uint32_t)*(uint16_t*)&hy << 16);
    lw = (uint32_t)*(uint16_t*)&lx | ((uint32_t)*(uint16_t*)&ly << 16);
}

// ---------------- prep kernels ----------------
__global__ void __launch_bounds__(256) xprep_k(const float* __restrict__ x) {
    size_t i = ((size_t)blockIdx.x * 256 + threadIdx.x) * 4;
    float4 v = *(const float4*)(x + i);
    float vv[4] = {v.x, v.y, v.z, v.w};
    __nv_bfloat16 h[4], l[4];
#pragma unroll
    for (int e = 0; e < 4; e++) bsplit(vv[e], &h[e], &l[e]);
    *(uint2*)(g_xh + i) = *(uint2*)h;
    *(uint2*)(g_xl + i) = *(uint2*)l;
}

__global__ void __launch_bounds__(256) wprep_k(const float* __restrict__ w, int N, int isattn) {
    __shared__ float ts[32][33];
    int tx = threadIdx.x & 31, ty = threadIdx.x >> 5;
    int n0 = blockIdx.x * 32, c0 = blockIdx.y * 32;
#pragma unroll
    for (int j = 0; j < 4; j++)
        ts[ty + j * 8][tx] = w[(size_t)(c0 + ty + j * 8) * N + n0 + tx];
    __syncthreads();
    __nv_bfloat16* th = isattn ? g_wah : g_wph;
    __nv_bfloat16* tl = isattn ? g_wal : g_wpl;
#pragma unroll
    for (int j = 0; j < 4; j++) {
        int n = n0 + ty + j * 8;
        float v = ts[tx][ty + j * 8];
        // fold (1/sqrt(D)) * log2(e) into q so softmax can use exp2
        if (isattn && n < CC) v *= 0.18033688011112042f;
        size_t a = (size_t)n * CC + c0 + tx;
        bsplit(v, &th[a], &tl[a]);
    }
}

// ---------------- mma.sync GEMM (qkv / proj) ----------------
template<int MODE>
__global__ void __launch_bounds__(256) gemm_mma(float* __restrict__ outp) {
    constexpr int NTILE = 128;
    constexpr int NC  = 32;
    constexpr int LDA = CC, LDB = CC;
    constexpr int WN  = NTILE / 2;
    constexpr int NN8 = WN / 8;
    constexpr int NJ  = WN / 16;
    constexpr int ASZ = 128 * 80;
    constexpr int BSZ = NTILE * 80;
    constexpr int STG = 2 * ASZ + 2 * BSZ;

    extern __shared__ char sm[];
    const uint32_t smu = smem_u32(sm);
    const int tid = threadIdx.x, lane = tid & 31, wid = tid >> 5;
    const int wm = wid & 3, wn = wid >> 2;
    const int warpM = wm * 32, warpN = wn * WN;
    const int nt = blockIdx.x, mt = blockIdx.y;
    const int m0 = mt * 128, n0 = nt * NTILE;

    const __nv_bfloat16 *a_h, *a_l, *b_h, *b_l;
    if constexpr (MODE == 0) {
        a_h = g_xh + (size_t)m0 * CC;  a_l = g_xl + (size_t)m0 * CC;
        b_h = g_wah + (size_t)n0 * CC; b_l = g_wal + (size_t)n0 * CC;
    } else {
        a_h = g_yh + (size_t)m0 * CC;  a_l = g_yl + (size_t)m0 * CC;
        b_h = g_wph + (size_t)n0 * CC; b_l = g_wpl + (size_t)n0 * CC;
    }

    auto load_stage = [&](int st, int kc) {
        const uint32_t s0 = smu + st * STG;
        const int k0 = kc * 32;
#pragma unroll
        for (int i0 = 0; i0 < 128 * 4; i0 += 256) {
            int i = i0 + tid, r = i >> 2, c = i & 3;
            uint32_t sa = s0 + r * 80 + c * 16;
            cp16(sa,       (const char*)(a_h + (size_t)r * LDA + k0) + c * 16);
            cp16(sa + ASZ, (const char*)(a_l + (size_t)r * LDA + k0) + c * 16);
        }
#pragma unroll
        for (int i0 = 0; i0 < NTILE * 4; i0 += 256) {
            int i = i0 + tid, r = i >> 2, c = i & 3;
            uint32_t sb2 = s0 + 2 * ASZ + r * 80 + c * 16;
            cp16(sb2,       (const char*)(b_h + (size_t)r * LDB + k0) + c * 16);
            cp16(sb2 + BSZ, (const char*)(b_l + (size_t)r * LDB + k0) + c * 16);
        }
        asm volatile("cp.async.commit_group;" ::: "memory");
    };

    const int grp = lane >> 3, r8 = lane & 7;
    const uint32_t aOff = (uint32_t)((warpM + r8 + (grp & 1) * 8) * 80 + (grp >> 1) * 16);
    const uint32_t bOff = (uint32_t)((warpN + r8 + (grp >> 1) * 8) * 80 + (grp & 1) * 16);

    float acc[2][NN8][4];
#pragma unroll
    for (int mi = 0; mi < 2; mi++)
#pragma unroll
        for (int ni = 0; ni < NN8; ni++)
#pragma unroll
            for (int e = 0; e < 4; e++) acc[mi][ni][e] = 0.f;

    load_stage(0, 0);

    for (int c = 0; c < NC; c++) {
        asm volatile("cp.async.wait_group 0;" ::: "memory");
        __syncthreads();
        // safe to overwrite the other stage: the sync above proves all warps
        // finished computing on it (they computed it in iter c-1 before arriving).
        if (c + 1 < NC) load_stage((c + 1) & 1, c + 1);

        const uint32_t sA = smu + (c & 1) * STG;
        const uint32_t sB = sA + 2 * ASZ;
#pragma unroll
        for (int kk = 0; kk < 2; kk++) {
            const uint32_t kb = kk * 32;
            uint32_t aFh[2][4], aFl[2][4], bF[NJ][4];
            ldm_x4(sA + aOff + kb,            aFh[0]);
            ldm_x4(sA + aOff + 16 * 80 + kb,  aFh[1]);
            ldm_x4(sA + ASZ + aOff + kb,           aFl[0]);
            ldm_x4(sA + ASZ + aOff + 16 * 80 + kb, aFl[1]);
#pragma unroll
            for (int nj = 0; nj < NJ; nj++)
                ldm_x4(sB + bOff + nj * 16 * 80 + kb, bF[nj]);
#pragma unroll
            for (int mi = 0; mi < 2; mi++)
#pragma unroll
                for (int ni = 0; ni < NN8; ni++)
                    mma16816(acc[mi][ni], aFh[mi], &bF[ni >> 1][(ni & 1) * 2]);
#pragma unroll
            for (int mi = 0; mi < 2; mi++)
#pragma unroll
                for (int ni = 0; ni < NN8; ni++)
                    mma16816(acc[mi][ni], aFl[mi], &bF[ni >> 1][(ni & 1) * 2]);
#pragma unroll
            for (int nj = 0; nj < NJ; nj++)
                ldm_x4(sB + BSZ + bOff + nj * 16 * 80 + kb, bF[nj]);
#pragma unroll
            for (int mi = 0; mi < 2; mi++)
#pragma unroll
                for (int ni = 0; ni < NN8; ni++)
                    mma16816(acc[mi][ni], aFh[mi], &bF[ni >> 1][(ni & 1) * 2]);
        }
    }

    const int row_l = lane >> 2, col_l = (lane & 3) * 2;
#pragma unroll
    for (int mi = 0; mi < 2; mi++) {
#pragma unroll
        for (int ni = 0; ni < NN8; ni++) {
            const int gr0 = m0 + warpM + mi * 16 + row_l;
            const int gc  = n0 + warpN + ni * 8 + col_l;
            const float* cc = acc[mi][ni];
            if constexpr (MODE == 0) {
                store_split(g_qkvh, g_qkvl, (size_t)gr0 * C3 + gc,       cc[0], cc[1]);
                store_split(g_qkvh, g_qkvl, (size_t)(gr0 + 8) * C3 + gc, cc[2], cc[3]);
            } else {
                *(float2*)(outp + (size_t)gr0 * CC + gc)       = make_float2(cc[0], cc[1]);
                *(float2*)(outp + (size_t)(gr0 + 8) * CC + gc) = make_float2(cc[2], cc[3]);
            }
        }
    }
}

// ---------------- fused flash attention (scores already in log2 domain) ----------------
__global__ void __launch_bounds__(256) flash_k() {
    constexpr int RSTR = 144;
    constexpr int BUF  = 64 * RSTR;
    constexpr int STG  = 4 * BUF;     // Kh,Kl,Vh,Vl
    constexpr int NT   = TT / 64;

    extern __shared__ char sm[];
    const uint32_t smu = smem_u32(sm);
    const int tid = threadIdx.x, lane = tid & 31, wid = tid >> 5;
    const int qt = blockIdx.x, bh = blockIdx.y;
    const int b = bh >> 4, h = bh & 15;
    const int r = lane >> 2, cq = (lane & 3) * 2;

    const size_t qbase = ((size_t)b * TT + qt * 128 + wid * 16) * C3 + h * DD;
    uint32_t qfh[4][4], qfl[4][4];
#pragma unroll
    for (int kc = 0; kc < 4; kc++)
#pragma unroll
        for (int e = 0; e < 4; e++) {
            size_t off = qbase + (size_t)(r + (e & 1) * 8) * C3 + kc * 16 + cq + (e >> 1) * 8;
            qfh[kc][e] = *(const uint32_t*)(g_qkvh + off);
            qfl[kc][e] = *(const uint32_t*)(g_qkvl + off);
        }

    float oacc[8][4];
#pragma unroll
    for (int nf = 0; nf < 8; nf++)
#pragma unroll
        for (int e = 0; e < 4; e++) oacc[nf][e] = 0.f;
    float m0r = -1e30f, m1r = -1e30f, l0r = 0.f, l1r = 0.f;

    const int grp = lane >> 3, r8 = lane & 7;
    const uint32_t kOff = (uint32_t)((r8 + (grp >> 1) * 8) * RSTR + (grp & 1) * 16);
    const uint32_t vOff = (uint32_t)(((grp & 1) * 8 + r8) * RSTR + (grp >> 1) * 16);
    const size_t kvb = (size_t)b * TT * C3 + h * DD;

    auto load_tile = [&](int kt, int st) {
        const uint32_t s0 = smu + st * STG;
        const int t0 = kt * 64;
#pragma unroll
        for (int it = 0; it < 2; it++) {
            int i = it * 256 + tid;
            int rr = i >> 3, c = i & 7;
            const __nv_bfloat16* gk  = g_qkvh + kvb + (size_t)(t0 + rr) * C3 + CC + c * 8;
            const __nv_bfloat16* gkl = g_qkvl + kvb + (size_t)(t0 + rr) * C3 + CC + c * 8;
            const __nv_bfloat16* gv  = g_qkvh + kvb + (size_t)(t0 + rr) * C3 + 2 * CC + c * 8;
            const __nv_bfloat16* gvl = g_qkvl + kvb + (size_t)(t0 + rr) * C3 + 2 * CC + c * 8;
            uint32_t sa = s0 + rr * RSTR + c * 16;
            cp16(sa,           gk);
            cp16(sa + BUF,     gkl);
            cp16(sa + 2 * BUF, gv);
            cp16(sa + 3 * BUF, gvl);
        }
        asm volatile("cp.async.commit_group;" ::: "memory");
    };

    load_tile(0, 0);

    for (int kt = 0; kt < NT; kt++) {
        asm volatile("cp.async.wait_group 0;" ::: "memory");
        __syncthreads();
        if (kt + 1 < NT) load_tile(kt + 1, (kt + 1) & 1);

        const uint32_t sK = smu + (kt & 1) * STG;
        const uint32_t sV = sK + 2 * BUF;

        // ---- S = Q K^T (3-pass split) ----
        float sacc[8][4];
#pragma unroll
        for (int nf = 0; nf < 8; nf++)
#pragma unroll
            for (int e = 0; e < 4; e++) sacc[nf][e] = 0.f;
#pragma unroll
        for (int kk = 0; kk < 4; kk++) {
            uint32_t bFh[4][4], bFl[4][4];
#pragma unroll
            for (int nj = 0; nj < 4; nj++)
                ldm_x4(sK + kOff + nj * 16 * RSTR + kk * 32, bFh[nj]);
#pragma unroll
            for (int nf = 0; nf < 8; nf++) {
                mma16816(sacc[nf], qfh[kk], &bFh[nf >> 1][(nf & 1) * 2]);
                mma16816(sacc[nf], qfl[kk], &bFh[nf >> 1][(nf & 1) * 2]);
            }
#pragma unroll
            for (int nj = 0; nj < 4; nj++)
                ldm_x4(sK + BUF + kOff + nj * 16 * RSTR + kk * 32, bFl[nj]);
#pragma unroll
            for (int nf = 0; nf < 8; nf++)
                mma16816(sacc[nf], qfh[kk], &bFl[nf >> 1][(nf & 1) * 2]);
        }

        // ---- online softmax (exp2 domain) ----
        float mx0 = -1e30f, mx1 = -1e30f;
#pragma unroll
        for (int nf = 0; nf < 8; nf++) {
            mx0 = fmaxf(mx0, fmaxf(sacc[nf][0], sacc[nf][1]));
            mx1 = fmaxf(mx1, fmaxf(sacc[nf][2], sacc[nf][3]));
        }
        mx0 = fmaxf(mx0, __shfl_xor_sync(0xffffffffu, mx0, 1));
        mx0 = fmaxf(mx0, __shfl_xor_sync(0xffffffffu, mx0, 2));
        mx1 = fmaxf(mx1, __shfl_xor_sync(0xffffffffu, mx1, 1));
        mx1 = fmaxf(mx1, __shfl_xor_sync(0xffffffffu, mx1, 2));
        const float mn0 = fmaxf(m0r, mx0), mn1 = fmaxf(m1r, mx1);
        const float al0 = exp2f(m0r - mn0), al1 = exp2f(m1r - mn1);
        float ls0 = 0.f, ls1 = 0.f;
#pragma unroll
        for (int nf = 0; nf < 8; nf++) {
            sacc[nf][0] = exp2f(sacc[nf][0] - mn0);
            sacc[nf][1] = exp2f(sacc[nf][1] - mn0);
            sacc[nf][2] = exp2f(sacc[nf][2] - mn1);
            sacc[nf][3] = exp2f(sacc[nf][3] - mn1);
            ls0 += sacc[nf][0] + sacc[nf][1];
            ls1 += sacc[nf][2] + sacc[nf][3];
        }
        ls0 += __shfl_xor_sync(0xffffffffu, ls0, 1);
        ls0 += __shfl_xor_sync(0xffffffffu, ls0, 2);
        ls1 += __shfl_xor_sync(0xffffffffu, ls1, 1);
        ls1 += __shfl_xor_sync(0xffffffffu, ls1, 2);
        l0r = l0r * al0 + ls0; m0r = mn0;
        l1r = l1r * al1 + ls1; m1r = mn1;
#pragma unroll
        for (int nf = 0; nf < 8; nf++) {
            oacc[nf][0] *= al0; oacc[nf][1] *= al0;
            oacc[nf][2] *= al1; oacc[nf][3] *= al1;
        }

        // ---- P -> bf16 hi/lo A-fragments ----
        uint32_t pfh[4][4], pfl[4][4];
#pragma unroll
        for (int kc = 0; kc < 4; kc++) {
            split2(sacc[2 * kc][0],     sacc[2 * kc][1],     pfh[kc][0], pfl[kc][0]);
            split2(sacc[2 * kc][2],     sacc[2 * kc][3],     pfh[kc][1], pfl[kc][1]);
            split2(sacc[2 * kc + 1][0], sacc[2 * kc + 1][1], pfh[kc][2], pfl[kc][2]);
            split2(sacc[2 * kc + 1][2], sacc[2 * kc + 1][3], pfh[kc][3], pfl[kc][3]);
        }

        // ---- O += P V (3-pass split) ----
#pragma unroll
        for (int kc = 0; kc < 4; kc++) {
            uint32_t vFh[4][4], vFl[4][4];
#pragma unroll
            for (int db = 0; db < 4; db++)
                ldm_x4t(sV + kc * 16 * RSTR + vOff + db * 32, vFh[db]);
#pragma unroll
            for (int nf = 0; nf < 8; nf++) {
                mma16816(oacc[nf], pfh[kc], &vFh[nf >> 1][(nf & 1) * 2]);
                mma16816(oacc[nf], pfl[kc], &vFh[nf >> 1][(nf & 1) * 2]);
            }
#pragma unroll
            for (int db = 0; db < 4; db++)
                ldm_x4t(sV + BUF + kc * 16 * RSTR + vOff + db * 32, vFl[db]);
#pragma unroll
            for (int nf = 0; nf < 8; nf++)
                mma16816(oacc[nf], pfh[kc], &vFl[nf >> 1][(nf & 1) * 2]);
        }
    }

    const float inv0 = 1.f / l0r, inv1 = 1.f / l1r;
    const size_t yb = ((size_t)b * TT + qt * 128 + wid * 16) * CC + h * DD;
#pragma unroll
    for (int nf = 0; nf < 8; nf++) {
        const int col = nf * 8 + cq;
        store_split(g_yh, g_yl, yb + (size_t)r * CC + col,
                    oacc[nf][0] * inv0, oacc[nf][1] * inv0);
        store_split(g_yh, g_yl, yb + (size_t)(r + 8) * CC + col,
                    oacc[nf][2] * inv1, oacc[nf][3] * inv1);
    }
}

// ---------------- host launcher ----------------
extern "C" void kernel_launch(void* const* d_in, const int* in_sizes, int n_in,
                              void* d_out, int out_size) {
    const float* x  = (const float*)d_in[0];
    const float* wa = (const float*)d_in[1];
    const float* wp = (const float*)d_in[2];
    float* out = (float*)d_out;

    constexpr int SM_GEMM  = 2 * (2 * 128 * 80 + 2 * 128 * 80);  // 81920
    constexpr int SM_FLASH = 2 * 4 * 64 * 144;                   // 73728

    cudaFuncSetAttribute((const void*)gemm_mma<0>, cudaFuncAttributeMaxDynamicSharedMemorySize, SM_GEMM);
    cudaFuncSetAttribute((const void*)gemm_mma<3>, cudaFuncAttributeMaxDynamicSharedMemorySize, SM_GEMM);
    cudaFuncSetAttribute((const void*)flash_k,     cudaFuncAttributeMaxDynamicSharedMemorySize, SM_FLASH);

    xprep_k<<<MROWS * CC / 1024, 256>>>(x);
    wprep_k<<<dim3(C3 / 32, CC / 32), 256>>>(wa, C3, 1);
    wprep_k<<<dim3(CC / 32, CC / 32), 256>>>(wp, CC, 0);

    gemm_mma<0><<<dim3(C3 / 128, MROWS / 128), 256, SM_GEMM>>>(nullptr);  // qkv
    flash_k<<<dim3(TT / 128, NBH), 256, SM_FLASH>>>();                    // fused attention
    gemm_mma<3><<<dim3(CC / 128, MROWS / 128), 256, SM_GEMM>>>(out);      // proj
}

// round 7
// speedup vs baseline: 7.8990x; 1.5269x over previous
#include <cuda_runtime.h>
#include <cuda_fp16.h>
#include <cstdint>

#define BB 2
#define TT 2048
#define CC 1024
#define HH 16
#define DD 64
#define C3 3072
#define MROWS 4096   // BB*TT
#define NBH 32       // BB*HH

// ---------------- device global scratch ----------------
__device__ __align__(16) __half g_xh[MROWS * CC], g_xl[MROWS * CC];   // x split
__device__ __align__(16) __half g_wa[C3 * CC];                        // w_attn^T fp16 (q cols pre-scaled)
__device__ __align__(16) __half g_wp[CC * CC];                        // w_proj^T fp16
__device__ __align__(16) __half g_qh[MROWS * CC], g_ql[MROWS * CC];   // q split [b,t,h*d]
__device__ __align__(16) __half g_k[MROWS * CC];                      // k fp16
__device__ __align__(16) __half g_v[MROWS * CC];                      // v fp16
__device__ __align__(16) __half g_yh[MROWS * CC], g_yl[MROWS * CC];   // attn out split

// ---------------- helpers ----------------
__device__ __forceinline__ uint32_t smem_u32(const void* p) {
    uint32_t a;
    asm("{ .reg .u64 t; cvta.to.shared.u64 t, %1; cvt.u32.u64 %0, t; }" : "=r"(a) : "l"(p));
    return a;
}
__device__ __forceinline__ void cp16(uint32_t s, const void* g) {
    asm volatile("cp.async.cg.shared.global [%0], [%1], 16;" :: "r"(s), "l"(g));
}
__device__ __forceinline__ void ldm_x4(uint32_t addr, uint32_t* r) {
    asm volatile("ldmatrix.sync.aligned.m8n8.x4.shared.b16 {%0,%1,%2,%3}, [%4];"
                 : "=r"(r[0]), "=r"(r[1]), "=r"(r[2]), "=r"(r[3]) : "r"(addr));
}
__device__ __forceinline__ void ldm_x4t(uint32_t addr, uint32_t* r) {
    asm volatile("ldmatrix.sync.aligned.m8n8.x4.trans.shared.b16 {%0,%1,%2,%3}, [%4];"
                 : "=r"(r[0]), "=r"(r[1]), "=r"(r[2]), "=r"(r[3]) : "r"(addr));
}
__device__ __forceinline__ void mma16816(float* c, const uint32_t* a, const uint32_t* b) {
    asm volatile("mma.sync.aligned.m16n8k16.row.col.f32.f16.f16.f32 "
                 "{%0,%1,%2,%3}, {%4,%5,%6,%7}, {%8,%9}, {%0,%1,%2,%3};"
                 : "+f"(c[0]), "+f"(c[1]), "+f"(c[2]), "+f"(c[3])
                 : "r"(a[0]), "r"(a[1]), "r"(a[2]), "r"(a[3]), "r"(b[0]), "r"(b[1]));
}
__device__ __forceinline__ void hsplit(float v, __half* h, __half* l) {
    __half hh = __float2half_rn(v);
    *h = hh;
    *l = __float2half_rn(v - __half2float(hh));
}
__device__ __forceinline__ void store_split(__half* H, __half* L, size_t idx, float x, float y) {
    __half2 h = __floats2half2_rn(x, y);
    __half2 l = __floats2half2_rn(x - __low2float(h), y - __high2float(h));
    *(__half2*)(H + idx) = h;
    *(__half2*)(L + idx) = l;
}
__device__ __forceinline__ void split2h(float x, float y, uint32_t& hw, uint32_t& lw) {
    __half2 h = __floats2half2_rn(x, y);
    __half2 l = __floats2half2_rn(x - __low2float(h), y - __high2float(h));
    hw = *(uint32_t*)&h;
    lw = *(uint32_t*)&l;
}

// ---------------- prep kernels ----------------
__global__ void __launch_bounds__(256) xprep_k(const float* __restrict__ x) {
    size_t i = ((size_t)blockIdx.x * 256 + threadIdx.x) * 4;
    float4 v = *(const float4*)(x + i);
    __half h[4], l[4];
    hsplit(v.x, &h[0], &l[0]);
    hsplit(v.y, &h[1], &l[1]);
    hsplit(v.z, &h[2], &l[2]);
    hsplit(v.w, &h[3], &l[3]);
    *(uint2*)(g_xh + i) = *(uint2*)h;
    *(uint2*)(g_xl + i) = *(uint2*)l;
}

// transpose w [CC][N] -> wt [N][CC] fp16; attn q-cols pre-scaled by (1/8)*log2(e)
__global__ void __launch_bounds__(256) wprep_k(const float* __restrict__ w, int N, int isattn) {
    __shared__ float ts[32][33];
    int tx = threadIdx.x & 31, ty = threadIdx.x >> 5;
    int n0 = blockIdx.x * 32, c0 = blockIdx.y * 32;
#pragma unroll
    for (int j = 0; j < 4; j++)
        ts[ty + j * 8][tx] = w[(size_t)(c0 + ty + j * 8) * N + n0 + tx];
    __syncthreads();
    __half* t = isattn ? g_wa : g_wp;
#pragma unroll
    for (int j = 0; j < 4; j++) {
        int n = n0 + ty + j * 8;
        float v = ts[tx][ty + j * 8];
        if (isattn && n < CC) v *= 0.18033688011112042f;  // (1/sqrt 64)*log2(e)
        t[(size_t)n * CC + c0 + tx] = __float2half_rn(v);
    }
}

// ---------------- mma.sync GEMM (qkv / proj), fp16 2-pass split-A ----------------
// MODE 0: qkv (x * w_attn^T) -> q split / k / v    M=4096 N=3072 K=1024
// MODE 3: proj(y * w_proj^T) -> out fp32           M=4096 N=1024 K=1024
template<int MODE>
__global__ void __launch_bounds__(256) gemm_mma(float* __restrict__ outp) {
    constexpr int NTILE = 128;
    constexpr int NC  = 32;           // k chunks of 32
    constexpr int LDA = CC, LDB = CC;
    constexpr int WN  = NTILE / 2;
    constexpr int NN8 = WN / 8;
    constexpr int NJ  = WN / 16;
    constexpr int ASZ = 128 * 80;     // one 128x32 fp16 tile, 80B rows
    constexpr int STG = 3 * ASZ;      // Ah, Al, B
    constexpr int NSTG = 3;

    extern __shared__ char sm[];
    const uint32_t smu = smem_u32(sm);
    const int tid = threadIdx.x, lane = tid & 31, wid = tid >> 5;
    const int wm = wid & 3, wn = wid >> 2;
    const int warpM = wm * 32, warpN = wn * WN;
    const int nt = blockIdx.x, mt = blockIdx.y;
    const int m0 = mt * 128, n0 = nt * NTILE;

    const __half *a_h, *a_l, *b_p;
    if constexpr (MODE == 0) {
        a_h = g_xh + (size_t)m0 * CC; a_l = g_xl + (size_t)m0 * CC;
        b_p = g_wa + (size_t)n0 * CC;
    } else {
        a_h = g_yh + (size_t)m0 * CC; a_l = g_yl + (size_t)m0 * CC;
        b_p = g_wp + (size_t)n0 * CC;
    }

    auto load_stage = [&](int st, int kc) {
        const uint32_t s0 = smu + st * STG;
        const int k0 = kc * 32;
#pragma unroll
        for (int i0 = 0; i0 < 128 * 4; i0 += 256) {
            int i = i0 + tid, r = i >> 2, c = i & 3;
            uint32_t sa = s0 + r * 80 + c * 16;
            cp16(sa,           (const char*)(a_h + (size_t)r * LDA + k0) + c * 16);
            cp16(sa + ASZ,     (const char*)(a_l + (size_t)r * LDA + k0) + c * 16);
            cp16(sa + 2 * ASZ, (const char*)(b_p + (size_t)r * LDB + k0) + c * 16);
        }
        asm volatile("cp.async.commit_group;" ::: "memory");
    };

    const int grp = lane >> 3, r8 = lane & 7;
    const uint32_t aOff = (uint32_t)((warpM + r8 + (grp & 1) * 8) * 80 + (grp >> 1) * 16);
    const uint32_t bOff = (uint32_t)((warpN + r8 + (grp >> 1) * 8) * 80 + (grp & 1) * 16);

    float acc[2][NN8][4];
#pragma unroll
    for (int mi = 0; mi < 2; mi++)
#pragma unroll
        for (int ni = 0; ni < NN8; ni++)
#pragma unroll
            for (int e = 0; e < 4; e++) acc[mi][ni][e] = 0.f;

    load_stage(0, 0);
    load_stage(1, 1);

    int st = 0;
    for (int c = 0; c < NC; c++) {
        if (c + 2 < NC) { asm volatile("cp.async.wait_group 1;" ::: "memory"); }
        else            { asm volatile("cp.async.wait_group 0;" ::: "memory"); }
        __syncthreads();
        if (c + 2 < NC) {
            int st2 = st + 2; if (st2 >= NSTG) st2 -= NSTG;
            load_stage(st2, c + 2);
        }

        const uint32_t sA = smu + st * STG;
        const uint32_t sB = sA + 2 * ASZ;
#pragma unroll
        for (int kk = 0; kk < 2; kk++) {
            const uint32_t kb = kk * 32;
            uint32_t aFh[2][4], aFl[2][4], bF[NJ][4];
            ldm_x4(sA + aOff + kb,                 aFh[0]);
            ldm_x4(sA + aOff + 16 * 80 + kb,       aFh[1]);
            ldm_x4(sA + ASZ + aOff + kb,           aFl[0]);
            ldm_x4(sA + ASZ + aOff + 16 * 80 + kb, aFl[1]);
#pragma unroll
            for (int nj = 0; nj < NJ; nj++)
                ldm_x4(sB + bOff + nj * 16 * 80 + kb, bF[nj]);
#pragma unroll
            for (int mi = 0; mi < 2; mi++)
#pragma unroll
                for (int ni = 0; ni < NN8; ni++)
                    mma16816(acc[mi][ni], aFh[mi], &bF[ni >> 1][(ni & 1) * 2]);
#pragma unroll
            for (int mi = 0; mi < 2; mi++)
#pragma unroll
                for (int ni = 0; ni < NN8; ni++)
                    mma16816(acc[mi][ni], aFl[mi], &bF[ni >> 1][(ni & 1) * 2]);
        }
        if (++st == NSTG) st = 0;
    }

    const int row_l = lane >> 2, col_l = (lane & 3) * 2;
#pragma unroll
    for (int mi = 0; mi < 2; mi++) {
#pragma unroll
        for (int ni = 0; ni < NN8; ni++) {
            const int gr0 = m0 + warpM + mi * 16 + row_l;
            const int gc  = n0 + warpN + ni * 8 + col_l;
            const float* cc = acc[mi][ni];
            if constexpr (MODE == 0) {
                if (gc < CC) {  // q: split (uniform per block since n0 % 1024 tiles cleanly)
                    store_split(g_qh, g_ql, (size_t)gr0 * CC + gc,       cc[0], cc[1]);
                    store_split(g_qh, g_ql, (size_t)(gr0 + 8) * CC + gc, cc[2], cc[3]);
                } else if (gc < 2 * CC) {
                    *(__half2*)(g_k + (size_t)gr0 * CC + gc - CC)       = __floats2half2_rn(cc[0], cc[1]);
                    *(__half2*)(g_k + (size_t)(gr0 + 8) * CC + gc - CC) = __floats2half2_rn(cc[2], cc[3]);
                } else {
                    *(__half2*)(g_v + (size_t)gr0 * CC + gc - 2 * CC)       = __floats2half2_rn(cc[0], cc[1]);
                    *(__half2*)(g_v + (size_t)(gr0 + 8) * CC + gc - 2 * CC) = __floats2half2_rn(cc[2], cc[3]);
                }
            } else {
                *(float2*)(outp + (size_t)gr0 * CC + gc)       = make_float2(cc[0], cc[1]);
                *(float2*)(outp + (size_t)(gr0 + 8) * CC + gc) = make_float2(cc[2], cc[3]);
            }
        }
    }
}

// ---------------- fused flash attention (fp16, scores in log2 domain) ----------------
__global__ void __launch_bounds__(256) flash_k() {
    constexpr int RSTR = 144;
    constexpr int BUF  = 64 * RSTR;   // one 64x64 fp16 tile
    constexpr int STG  = 2 * BUF;     // K, V
    constexpr int NSTG = 3;
    constexpr int NT   = TT / 64;

    extern __shared__ char sm[];
    const uint32_t smu = smem_u32(sm);
    const int tid = threadIdx.x, lane = tid & 31, wid = tid >> 5;
    const int qt = blockIdx.x, bh = blockIdx.y;
    const int b = bh >> 4, h = bh & 15;
    const int r = lane >> 2, cq = (lane & 3) * 2;

    // Q fragments (hi/lo) straight from global, reused for all 32 key tiles
    const size_t qbase = ((size_t)b * TT + qt * 128 + wid * 16) * CC + h * DD;
    uint32_t qfh[4][4], qfl[4][4];
#pragma unroll
    for (int kc = 0; kc < 4; kc++)
#pragma unroll
        for (int e = 0; e < 4; e++) {
            size_t off = qbase + (size_t)(r + (e & 1) * 8) * CC + kc * 16 + cq + (e >> 1) * 8;
            qfh[kc][e] = *(const uint32_t*)(g_qh + off);
            qfl[kc][e] = *(const uint32_t*)(g_ql + off);
        }

    float oacc[8][4];
#pragma unroll
    for (int nf = 0; nf < 8; nf++)
#pragma unroll
        for (int e = 0; e < 4; e++) oacc[nf][e] = 0.f;
    float m0r = -1e30f, m1r = -1e30f, l0r = 0.f, l1r = 0.f;

    const int grp = lane >> 3, r8 = lane & 7;
    const uint32_t kOff = (uint32_t)((r8 + (grp >> 1) * 8) * RSTR + (grp & 1) * 16);
    const uint32_t vOff = (uint32_t)(((grp & 1) * 8 + r8) * RSTR + (grp >> 1) * 16);
    const size_t kvb = (size_t)b * TT * CC + h * DD;

    auto load_tile = [&](int kt, int st) {
        const uint32_t s0 = smu + st * STG;
        const int t0 = kt * 64;
#pragma unroll
        for (int it = 0; it < 2; it++) {
            int i = it * 256 + tid;
            int rr = i >> 3, c = i & 7;
            uint32_t sa = s0 + rr * RSTR + c * 16;
            cp16(sa,       (const char*)(g_k + kvb + (size_t)(t0 + rr) * CC) + c * 16);
            cp16(sa + BUF, (const char*)(g_v + kvb + (size_t)(t0 + rr) * CC) + c * 16);
        }
        asm volatile("cp.async.commit_group;" ::: "memory");
    };

    load_tile(0, 0);
    load_tile(1, 1);

    int st = 0;
    for (int kt = 0; kt < NT; kt++) {
        if (kt + 2 < NT) { asm volatile("cp.async.wait_group 1;" ::: "memory"); }
        else             { asm volatile("cp.async.wait_group 0;" ::: "memory"); }
        __syncthreads();
        if (kt + 2 < NT) {
            int st2 = st + 2; if (st2 >= NSTG) st2 -= NSTG;
            load_tile(kt + 2, st2);
        }

        const uint32_t sK = smu + st * STG;
        const uint32_t sV = sK + BUF;

        // ---- S = Q K^T (2-pass split-Q) ----
        float sacc[8][4];
#pragma unroll
        for (int nf = 0; nf < 8; nf++)
#pragma unroll
            for (int e = 0; e < 4; e++) sacc[nf][e] = 0.f;
#pragma unroll
        for (int kk = 0; kk < 4; kk++) {
            uint32_t bF[4][4];
#pragma unroll
            for (int nj = 0; nj < 4; nj++)
                ldm_x4(sK + kOff + nj * 16 * RSTR + kk * 32, bF[nj]);
#pragma unroll
            for (int nf = 0; nf < 8; nf++) {
                mma16816(sacc[nf], qfh[kk], &bF[nf >> 1][(nf & 1) * 2]);
                mma16816(sacc[nf], qfl[kk], &bF[nf >> 1][(nf & 1) * 2]);
            }
        }

        // ---- online softmax (exp2 domain) ----
        float mx0 = -1e30f, mx1 = -1e30f;
#pragma unroll
        for (int nf = 0; nf < 8; nf++) {
            mx0 = fmaxf(mx0, fmaxf(sacc[nf][0], sacc[nf][1]));
            mx1 = fmaxf(mx1, fmaxf(sacc[nf][2], sacc[nf][3]));
        }
        mx0 = fmaxf(mx0, __shfl_xor_sync(0xffffffffu, mx0, 1));
        mx0 = fmaxf(mx0, __shfl_xor_sync(0xffffffffu, mx0, 2));
        mx1 = fmaxf(mx1, __shfl_xor_sync(0xffffffffu, mx1, 1));
        mx1 = fmaxf(mx1, __shfl_xor_sync(0xffffffffu, mx1, 2));
        const float mn0 = fmaxf(m0r, mx0), mn1 = fmaxf(m1r, mx1);
        const float al0 = exp2f(m0r - mn0), al1 = exp2f(m1r - mn1);
        float ls0 = 0.f, ls1 = 0.f;
#pragma unroll
        for (int nf = 0; nf < 8; nf++) {
            sacc[nf][0] = exp2f(sacc[nf][0] - mn0);
            sacc[nf][1] = exp2f(sacc[nf][1] - mn0);
            sacc[nf][2] = exp2f(sacc[nf][2] - mn1);
            sacc[nf][3] = exp2f(sacc[nf][3] - mn1);
            ls0 += sacc[nf][0] + sacc[nf][1];
            ls1 += sacc[nf][2] + sacc[nf][3];
        }
        ls0 += __shfl_xor_sync(0xffffffffu, ls0, 1);
        ls0 += __shfl_xor_sync(0xffffffffu, ls0, 2);
        ls1 += __shfl_xor_sync(0xffffffffu, ls1, 1);
        ls1 += __shfl_xor_sync(0xffffffffu, ls1, 2);
        l0r = l0r * al0 + ls0; m0r = mn0;
        l1r = l1r * al1 + ls1; m1r = mn1;
#pragma unroll
        for (int nf = 0; nf < 8; nf++) {
            oacc[nf][0] *= al0; oacc[nf][1] *= al0;
            oacc[nf][2] *= al1; oacc[nf][3] *= al1;
        }

        // ---- P -> fp16 hi/lo A-fragments (accumulator layout identity) ----
        uint32_t pfh[4][4], pfl[4][4];
#pragma unroll
        for (int kc = 0; kc < 4; kc++) {
            split2h(sacc[2 * kc][0],     sacc[2 * kc][1],     pfh[kc][0], pfl[kc][0]);
            split2h(sacc[2 * kc][2],     sacc[2 * kc][3],     pfh[kc][1], pfl[kc][1]);
            split2h(sacc[2 * kc + 1][0], sacc[2 * kc + 1][1], pfh[kc][2], pfl[kc][2]);
            split2h(sacc[2 * kc + 1][2], sacc[2 * kc + 1][3], pfh[kc][3], pfl[kc][3]);
        }

        // ---- O += P V (2-pass split-P), V via ldmatrix.trans ----
#pragma unroll
        for (int kc = 0; kc < 4; kc++) {
            uint32_t vF[4][4];
#pragma unroll
            for (int db = 0; db < 4; db++)
                ldm_x4t(sV + kc * 16 * RSTR + vOff + db * 32, vF[db]);
#pragma unroll
            for (int nf = 0; nf < 8; nf++) {
                mma16816(oacc[nf], pfh[kc], &vF[nf >> 1][(nf & 1) * 2]);
                mma16816(oacc[nf], pfl[kc], &vF[nf >> 1][(nf & 1) * 2]);
            }
        }
        if (++st == NSTG) st = 0;
    }

    const float inv0 = 1.f / l0r, inv1 = 1.f / l1r;
    const size_t yb = ((size_t)b * TT + qt * 128 + wid * 16) * CC + h * DD;
#pragma unroll
    for (int nf = 0; nf < 8; nf++) {
        const int col = nf * 8 + cq;
        store_split(g_yh, g_yl, yb + (size_t)r * CC + col,
                    oacc[nf][0] * inv0, oacc[nf][1] * inv0);
        store_split(g_yh, g_yl, yb + (size_t)(r + 8) * CC + col,
                    oacc[nf][2] * inv1, oacc[nf][3] * inv1);
    }
}

// ---------------- host launcher ----------------
extern "C" void kernel_launch(void* const* d_in, const int* in_sizes, int n_in,
                              void* d_out, int out_size) {
    const float* x  = (const float*)d_in[0];
    const float* wa = (const float*)d_in[1];
    const float* wp = (const float*)d_in[2];
    float* out = (float*)d_out;

    constexpr int SM_GEMM  = 3 * 3 * 128 * 80;   // 92160 (3 stages x [Ah,Al,B])
    constexpr int SM_FLASH = 3 * 2 * 64 * 144;   // 55296 (3 stages x [K,V])

    cudaFuncSetAttribute((const void*)gemm_mma<0>, cudaFuncAttributeMaxDynamicSharedMemorySize, SM_GEMM);
    cudaFuncSetAttribute((const void*)gemm_mma<3>, cudaFuncAttributeMaxDynamicSharedMemorySize, SM_GEMM);
    cudaFuncSetAttribute((const void*)flash_k,     cudaFuncAttributeMaxDynamicSharedMemorySize, SM_FLASH);

    xprep_k<<<MROWS * CC / 1024, 256>>>(x);
    wprep_k<<<dim3(C3 / 32, CC / 32), 256>>>(wa, C3, 1);
    wprep_k<<<dim3(CC / 32, CC / 32), 256>>>(wp, CC, 0);

    gemm_mma<0><<<dim3(C3 / 128, MROWS / 128), 256, SM_GEMM>>>(nullptr);  // qkv
    flash_k<<<dim3(TT / 128, NBH), 256, SM_FLASH>>>();                    // fused attention
    gemm_mma<3><<<dim3(CC / 128, MROWS / 128), 256, SM_GEMM>>>(out);      // proj
}

// round 8
// speedup vs baseline: 9.7985x; 1.2405x over previous
#include <cuda_runtime.h>
#include <cuda_fp16.h>
#include <cstdint>

#define BB 2
#define TT 2048
#define CC 1024
#define HH 16
#define DD 64
#define C3 3072
#define MROWS 4096   // BB*TT
#define NBH 32       // BB*HH

// ---------------- device global scratch ----------------
__device__ __align__(16) __half g_xh[MROWS * CC], g_xl[MROWS * CC];   // x split
__device__ __align__(16) __half g_wa[C3 * CC];                        // w_attn^T fp16 (q cols pre-scaled)
__device__ __align__(16) __half g_wp[CC * CC];                        // w_proj^T fp16
__device__ __align__(16) __half g_qh[MROWS * CC], g_ql[MROWS * CC];   // q split [b,t,h*d]
__device__ __align__(16) __half g_k[MROWS * CC];                      // k fp16
__device__ __align__(16) __half g_v[MROWS * CC];                      // v fp16
__device__ __align__(16) __half g_y[MROWS * CC];                      // attn out fp16

// ---------------- helpers ----------------
__device__ __forceinline__ uint32_t smem_u32(const void* p) {
    uint32_t a;
    asm("{ .reg .u64 t; cvta.to.shared.u64 t, %1; cvt.u32.u64 %0, t; }" : "=r"(a) : "l"(p));
    return a;
}
__device__ __forceinline__ void cp16(uint32_t s, const void* g) {
    asm volatile("cp.async.cg.shared.global [%0], [%1], 16;" :: "r"(s), "l"(g));
}
__device__ __forceinline__ void ldm_x4(uint32_t addr, uint32_t* r) {
    asm volatile("ldmatrix.sync.aligned.m8n8.x4.shared.b16 {%0,%1,%2,%3}, [%4];"
                 : "=r"(r[0]), "=r"(r[1]), "=r"(r[2]), "=r"(r[3]) : "r"(addr));
}
__device__ __forceinline__ void ldm_x4t(uint32_t addr, uint32_t* r) {
    asm volatile("ldmatrix.sync.aligned.m8n8.x4.trans.shared.b16 {%0,%1,%2,%3}, [%4];"
                 : "=r"(r[0]), "=r"(r[1]), "=r"(r[2]), "=r"(r[3]) : "r"(addr));
}
__device__ __forceinline__ void mma16816(float* c, const uint32_t* a, const uint32_t* b) {
    asm volatile("mma.sync.aligned.m16n8k16.row.col.f32.f16.f16.f32 "
                 "{%0,%1,%2,%3}, {%4,%5,%6,%7}, {%8,%9}, {%0,%1,%2,%3};"
                 : "+f"(c[0]), "+f"(c[1]), "+f"(c[2]), "+f"(c[3])
                 : "r"(a[0]), "r"(a[1]), "r"(a[2]), "r"(a[3]), "r"(b[0]), "r"(b[1]));
}
__device__ __forceinline__ void hsplit(float v, __half* h, __half* l) {
    __half hh = __float2half_rn(v);
    *h = hh;
    *l = __float2half_rn(v - __half2float(hh));
}
__device__ __forceinline__ void store_split(__half* H, __half* L, size_t idx, float x, float y) {
    __half2 h = __floats2half2_rn(x, y);
    __half2 l = __floats2half2_rn(x - __low2float(h), y - __high2float(h));
    *(__half2*)(H + idx) = h;
    *(__half2*)(L + idx) = l;
}
__device__ __forceinline__ uint32_t pack2h(float x, float y) {
    __half2 h = __floats2half2_rn(x, y);
    return *(uint32_t*)&h;
}

// ---------------- prep kernels ----------------
__global__ void __launch_bounds__(256) xprep_k(const float* __restrict__ x) {
    size_t i = ((size_t)blockIdx.x * 256 + threadIdx.x) * 4;
    float4 v = *(const float4*)(x + i);
    __half h[4], l[4];
    hsplit(v.x, &h[0], &l[0]);
    hsplit(v.y, &h[1], &l[1]);
    hsplit(v.z, &h[2], &l[2]);
    hsplit(v.w, &h[3], &l[3]);
    *(uint2*)(g_xh + i) = *(uint2*)h;
    *(uint2*)(g_xl + i) = *(uint2*)l;
}

// transpose w [CC][N] -> wt [N][CC] fp16; attn q-cols pre-scaled by (1/8)*log2(e)
__global__ void __launch_bounds__(256) wprep_k(const float* __restrict__ w, int N, int isattn) {
    __shared__ float ts[32][33];
    int tx = threadIdx.x & 31, ty = threadIdx.x >> 5;
    int n0 = blockIdx.x * 32, c0 = blockIdx.y * 32;
#pragma unroll
    for (int j = 0; j < 4; j++)
        ts[ty + j * 8][tx] = w[(size_t)(c0 + ty + j * 8) * N + n0 + tx];
    __syncthreads();
    __half* t = isattn ? g_wa : g_wp;
#pragma unroll
    for (int j = 0; j < 4; j++) {
        int n = n0 + ty + j * 8;
        float v = ts[tx][ty + j * 8];
        if (isattn && n < CC) v *= 0.18033688011112042f;  // (1/sqrt 64)*log2(e)
        t[(size_t)n * CC + c0 + tx] = __float2half_rn(v);
    }
}

// ---------------- mma.sync GEMM (qkv 2-pass / proj 1-pass) ----------------
// MODE 0: qkv (x * w_attn^T) -> q split / k / v    M=4096 N=3072 K=1024, split-A
// MODE 3: proj(y * w_proj^T) -> out fp32           M=4096 N=1024 K=1024, single-A
template<int MODE>
__global__ void __launch_bounds__(256) gemm_mma(float* __restrict__ outp) {
    constexpr int NPASS = (MODE == 0) ? 2 : 1;
    constexpr int NTILE = 128;
    constexpr int NC  = 32;           // k chunks of 32
    constexpr int LDA = CC, LDB = CC;
    constexpr int WN  = NTILE / 2;
    constexpr int NN8 = WN / 8;
    constexpr int NJ  = WN / 16;
    constexpr int ASZ = 128 * 80;     // one 128x32 fp16 tile, 80B rows
    constexpr int STG = (NPASS + 1) * ASZ;  // [Ah,(Al),B]
    constexpr int NSTG = 3;

    extern __shared__ char sm[];
    const uint32_t smu = smem_u32(sm);
    const int tid = threadIdx.x, lane = tid & 31, wid = tid >> 5;
    const int wm = wid & 3, wn = wid >> 2;
    const int warpM = wm * 32, warpN = wn * WN;
    const int nt = blockIdx.x, mt = blockIdx.y;
    const int m0 = mt * 128, n0 = nt * NTILE;

    const __half *a_h, *a_l, *b_p;
    if constexpr (MODE == 0) {
        a_h = g_xh + (size_t)m0 * CC; a_l = g_xl + (size_t)m0 * CC;
        b_p = g_wa + (size_t)n0 * CC;
    } else {
        a_h = g_y + (size_t)m0 * CC;  a_l = nullptr;
        b_p = g_wp + (size_t)n0 * CC;
    }

    auto load_stage = [&](int st, int kc) {
        const uint32_t s0 = smu + st * STG;
        const int k0 = kc * 32;
#pragma unroll
        for (int i0 = 0; i0 < 128 * 4; i0 += 256) {
            int i = i0 + tid, r = i >> 2, c = i & 3;
            uint32_t sa = s0 + r * 80 + c * 16;
            cp16(sa, (const char*)(a_h + (size_t)r * LDA + k0) + c * 16);
            if constexpr (NPASS == 2)
                cp16(sa + ASZ, (const char*)(a_l + (size_t)r * LDA + k0) + c * 16);
            cp16(sa + NPASS * ASZ, (const char*)(b_p + (size_t)r * LDB + k0) + c * 16);
        }
        asm volatile("cp.async.commit_group;" ::: "memory");
    };

    const int grp = lane >> 3, r8 = lane & 7;
    const uint32_t aOff = (uint32_t)((warpM + r8 + (grp & 1) * 8) * 80 + (grp >> 1) * 16);
    const uint32_t bOff = (uint32_t)((warpN + r8 + (grp >> 1) * 8) * 80 + (grp & 1) * 16);

    float acc[2][NN8][4];
#pragma unroll
    for (int mi = 0; mi < 2; mi++)
#pragma unroll
        for (int ni = 0; ni < NN8; ni++)
#pragma unroll
            for (int e = 0; e < 4; e++) acc[mi][ni][e] = 0.f;

    load_stage(0, 0);
    load_stage(1, 1);

    int st = 0;
    for (int c = 0; c < NC; c++) {
        if (c + 2 < NC) { asm volatile("cp.async.wait_group 1;" ::: "memory"); }
        else            { asm volatile("cp.async.wait_group 0;" ::: "memory"); }
        __syncthreads();
        if (c + 2 < NC) {
            int st2 = st + 2; if (st2 >= NSTG) st2 -= NSTG;
            load_stage(st2, c + 2);
        }

        const uint32_t sA = smu + st * STG;
        const uint32_t sB = sA + NPASS * ASZ;
#pragma unroll
        for (int kk = 0; kk < 2; kk++) {
            const uint32_t kb = kk * 32;
            uint32_t aFh[2][4], aFl[2][4], bF[NJ][4];
            ldm_x4(sA + aOff + kb,           aFh[0]);
            ldm_x4(sA + aOff + 16 * 80 + kb, aFh[1]);
            if constexpr (NPASS == 2) {
                ldm_x4(sA + ASZ + aOff + kb,           aFl[0]);
                ldm_x4(sA + ASZ + aOff + 16 * 80 + kb, aFl[1]);
            }
#pragma unroll
            for (int nj = 0; nj < NJ; nj++)
                ldm_x4(sB + bOff + nj * 16 * 80 + kb, bF[nj]);
#pragma unroll
            for (int mi = 0; mi < 2; mi++)
#pragma unroll
                for (int ni = 0; ni < NN8; ni++)
                    mma16816(acc[mi][ni], aFh[mi], &bF[ni >> 1][(ni & 1) * 2]);
            if constexpr (NPASS == 2) {
#pragma unroll
                for (int mi = 0; mi < 2; mi++)
#pragma unroll
                    for (int ni = 0; ni < NN8; ni++)
                        mma16816(acc[mi][ni], aFl[mi], &bF[ni >> 1][(ni & 1) * 2]);
            }
        }
        if (++st == NSTG) st = 0;
    }

    const int row_l = lane >> 2, col_l = (lane & 3) * 2;
#pragma unroll
    for (int mi = 0; mi < 2; mi++) {
#pragma unroll
        for (int ni = 0; ni < NN8; ni++) {
            const int gr0 = m0 + warpM + mi * 16 + row_l;
            const int gc  = n0 + warpN + ni * 8 + col_l;
            const float* cc = acc[mi][ni];
            if constexpr (MODE == 0) {
                if (gc < CC) {  // q: split
                    store_split(g_qh, g_ql, (size_t)gr0 * CC + gc,       cc[0], cc[1]);
                    store_split(g_qh, g_ql, (size_t)(gr0 + 8) * CC + gc, cc[2], cc[3]);
                } else if (gc < 2 * CC) {
                    *(uint32_t*)(g_k + (size_t)gr0 * CC + gc - CC)       = pack2h(cc[0], cc[1]);
                    *(uint32_t*)(g_k + (size_t)(gr0 + 8) * CC + gc - CC) = pack2h(cc[2], cc[3]);
                } else {
                    *(uint32_t*)(g_v + (size_t)gr0 * CC + gc - 2 * CC)       = pack2h(cc[0], cc[1]);
                    *(uint32_t*)(g_v + (size_t)(gr0 + 8) * CC + gc - 2 * CC) = pack2h(cc[2], cc[3]);
                }
            } else {
                *(float2*)(outp + (size_t)gr0 * CC + gc)       = make_float2(cc[0], cc[1]);
                *(float2*)(outp + (size_t)(gr0 + 8) * CC + gc) = make_float2(cc[2], cc[3]);
            }
        }
    }
}

// ---------------- fused flash attention (fp16, scores in log2 domain) ----------------
__global__ void __launch_bounds__(256) flash_k() {
    constexpr int RSTR = 144;
    constexpr int BUF  = 64 * RSTR;   // one 64x64 fp16 tile
    constexpr int STG  = 2 * BUF;     // K, V
    constexpr int NSTG = 3;
    constexpr int NT   = TT / 64;

    extern __shared__ char sm[];
    const uint32_t smu = smem_u32(sm);
    const int tid = threadIdx.x, lane = tid & 31, wid = tid >> 5;
    const int qt = blockIdx.x, bh = blockIdx.y;
    const int b = bh >> 4, h = bh & 15;
    const int r = lane >> 2, cq = (lane & 3) * 2;

    // Q fragments (hi/lo) straight from global, reused for all 32 key tiles
    const size_t qbase = ((size_t)b * TT + qt * 128 + wid * 16) * CC + h * DD;
    uint32_t qfh[4][4], qfl[4][4];
#pragma unroll
    for (int kc = 0; kc < 4; kc++)
#pragma unroll
        for (int e = 0; e < 4; e++) {
            size_t off = qbase + (size_t)(r + (e & 1) * 8) * CC + kc * 16 + cq + (e >> 1) * 8;
            qfh[kc][e] = *(const uint32_t*)(g_qh + off);
            qfl[kc][e] = *(const uint32_t*)(g_ql + off);
        }

    float oacc[8][4];
#pragma unroll
    for (int nf = 0; nf < 8; nf++)
#pragma unroll
        for (int e = 0; e < 4; e++) oacc[nf][e] = 0.f;
    float m0r = -1e30f, m1r = -1e30f, l0r = 0.f, l1r = 0.f;

    const int grp = lane >> 3, r8 = lane & 7;
    const uint32_t kOff = (uint32_t)((r8 + (grp >> 1) * 8) * RSTR + (grp & 1) * 16);
    const uint32_t vOff = (uint32_t)(((grp & 1) * 8 + r8) * RSTR + (grp >> 1) * 16);
    const size_t kvb = (size_t)b * TT * CC + h * DD;

    auto load_tile = [&](int kt, int st) {
        const uint32_t s0 = smu + st * STG;
        const int t0 = kt * 64;
#pragma unroll
        for (int it = 0; it < 2; it++) {
            int i = it * 256 + tid;
            int rr = i >> 3, c = i & 7;
            uint32_t sa = s0 + rr * RSTR + c * 16;
            cp16(sa,       (const char*)(g_k + kvb + (size_t)(t0 + rr) * CC) + c * 16);
            cp16(sa + BUF, (const char*)(g_v + kvb + (size_t)(t0 + rr) * CC) + c * 16);
        }
        asm volatile("cp.async.commit_group;" ::: "memory");
    };

    load_tile(0, 0);
    load_tile(1, 1);

    int st = 0;
    for (int kt = 0; kt < NT; kt++) {
        if (kt + 2 < NT) { asm volatile("cp.async.wait_group 1;" ::: "memory"); }
        else             { asm volatile("cp.async.wait_group 0;" ::: "memory"); }
        __syncthreads();
        if (kt + 2 < NT) {
            int st2 = st + 2; if (st2 >= NSTG) st2 -= NSTG;
            load_tile(kt + 2, st2);
        }

        const uint32_t sK = smu + st * STG;
        const uint32_t sV = sK + BUF;

        // ---- S = Q K^T (2-pass split-Q) ----
        float sacc[8][4];
#pragma unroll
        for (int nf = 0; nf < 8; nf++)
#pragma unroll
            for (int e = 0; e < 4; e++) sacc[nf][e] = 0.f;
#pragma unroll
        for (int kk = 0; kk < 4; kk++) {
            uint32_t bF[4][4];
#pragma unroll
            for (int nj = 0; nj < 4; nj++)
                ldm_x4(sK + kOff + nj * 16 * RSTR + kk * 32, bF[nj]);
#pragma unroll
            for (int nf = 0; nf < 8; nf++) {
                mma16816(sacc[nf], qfh[kk], &bF[nf >> 1][(nf & 1) * 2]);
                mma16816(sacc[nf], qfl[kk], &bF[nf >> 1][(nf & 1) * 2]);
            }
        }

        // ---- online softmax (exp2 domain) ----
        float mx0 = -1e30f, mx1 = -1e30f;
#pragma unroll
        for (int nf = 0; nf < 8; nf++) {
            mx0 = fmaxf(mx0, fmaxf(sacc[nf][0], sacc[nf][1]));
            mx1 = fmaxf(mx1, fmaxf(sacc[nf][2], sacc[nf][3]));
        }
        mx0 = fmaxf(mx0, __shfl_xor_sync(0xffffffffu, mx0, 1));
        mx0 = fmaxf(mx0, __shfl_xor_sync(0xffffffffu, mx0, 2));
        mx1 = fmaxf(mx1, __shfl_xor_sync(0xffffffffu, mx1, 1));
        mx1 = fmaxf(mx1, __shfl_xor_sync(0xffffffffu, mx1, 2));
        const float mn0 = fmaxf(m0r, mx0), mn1 = fmaxf(m1r, mx1);
        const float al0 = exp2f(m0r - mn0), al1 = exp2f(m1r - mn1);
        float ls0 = 0.f, ls1 = 0.f;
#pragma unroll
        for (int nf = 0; nf < 8; nf++) {
            sacc[nf][0] = exp2f(sacc[nf][0] - mn0);
            sacc[nf][1] = exp2f(sacc[nf][1] - mn0);
            sacc[nf][2] = exp2f(sacc[nf][2] - mn1);
            sacc[nf][3] = exp2f(sacc[nf][3] - mn1);
            ls0 += sacc[nf][0] + sacc[nf][1];
            ls1 += sacc[nf][2] + sacc[nf][3];
        }
        ls0 += __shfl_xor_sync(0xffffffffu, ls0, 1);
        ls0 += __shfl_xor_sync(0xffffffffu, ls0, 2);
        ls1 += __shfl_xor_sync(0xffffffffu, ls1, 1);
        ls1 += __shfl_xor_sync(0xffffffffu, ls1, 2);
        l0r = l0r * al0 + ls0; m0r = mn0;
        l1r = l1r * al1 + ls1; m1r = mn1;
#pragma unroll
        for (int nf = 0; nf < 8; nf++) {
            oacc[nf][0] *= al0; oacc[nf][1] *= al0;
            oacc[nf][2] *= al1; oacc[nf][3] *= al1;
        }

        // ---- P -> single fp16 A-fragments (accumulator layout identity) ----
        uint32_t pf[4][4];
#pragma unroll
        for (int kc = 0; kc < 4; kc++) {
            pf[kc][0] = pack2h(sacc[2 * kc][0],     sacc[2 * kc][1]);
            pf[kc][1] = pack2h(sacc[2 * kc][2],     sacc[2 * kc][3]);
            pf[kc][2] = pack2h(sacc[2 * kc + 1][0], sacc[2 * kc + 1][1]);
            pf[kc][3] = pack2h(sacc[2 * kc + 1][2], sacc[2 * kc + 1][3]);
        }

        // ---- O += P V (single pass), V via ldmatrix.trans ----
#pragma unroll
        for (int kc = 0; kc < 4; kc++) {
            uint32_t vF[4][4];
#pragma unroll
            for (int db = 0; db < 4; db++)
                ldm_x4t(sV + kc * 16 * RSTR + vOff + db * 32, vF[db]);
#pragma unroll
            for (int nf = 0; nf < 8; nf++)
                mma16816(oacc[nf], pf[kc], &vF[nf >> 1][(nf & 1) * 2]);
        }
        if (++st == NSTG) st = 0;
    }

    const float inv0 = 1.f / l0r, inv1 = 1.f / l1r;
    const size_t yb = ((size_t)b * TT + qt * 128 + wid * 16) * CC + h * DD;
#pragma unroll
    for (int nf = 0; nf < 8; nf++) {
        const int col = nf * 8 + cq;
        *(uint32_t*)(g_y + yb + (size_t)r * CC + col) =
            pack2h(oacc[nf][0] * inv0, oacc[nf][1] * inv0);
        *(uint32_t*)(g_y + yb + (size_t)(r + 8) * CC + col) =
            pack2h(oacc[nf][2] * inv1, oacc[nf][3] * inv1);
    }
}

// ---------------- host launcher ----------------
extern "C" void kernel_launch(void* const* d_in, const int* in_sizes, int n_in,
                              void* d_out, int out_size) {
    const float* x  = (const float*)d_in[0];
    const float* wa = (const float*)d_in[1];
    const float* wp = (const float*)d_in[2];
    float* out = (float*)d_out;

    constexpr int SM_QKV   = 3 * 3 * 128 * 80;   // 92160 (3 stages x [Ah,Al,B])
    constexpr int SM_PROJ  = 3 * 2 * 128 * 80;   // 61440 (3 stages x [A,B])
    constexpr int SM_FLASH = 3 * 2 * 64 * 144;   // 55296 (3 stages x [K,V])

    cudaFuncSetAttribute((const void*)gemm_mma<0>, cudaFuncAttributeMaxDynamicSharedMemorySize, SM_QKV);
    cudaFuncSetAttribute((const void*)gemm_mma<3>, cudaFuncAttributeMaxDynamicSharedMemorySize, SM_PROJ);
    cudaFuncSetAttribute((const void*)flash_k,     cudaFuncAttributeMaxDynamicSharedMemorySize, SM_FLASH);

    xprep_k<<<MROWS * CC / 1024, 256>>>(x);
    wprep_k<<<dim3(C3 / 32, CC / 32), 256>>>(wa, C3, 1);
    wprep_k<<<dim3(CC / 32, CC / 32), 256>>>(wp, CC, 0);

    gemm_mma<0><<<dim3(C3 / 128, MROWS / 128), 256, SM_QKV>>>(nullptr);   // qkv
    flash_k<<<dim3(TT / 128, NBH), 256, SM_FLASH>>>();                    // fused attention
    gemm_mma<3><<<dim3(CC / 128, MROWS / 128), 256, SM_PROJ>>>(out);      // proj
}

// round 9
// speedup vs baseline: 12.1864x; 1.2437x over previous
#include <cuda_runtime.h>
#include <cuda_fp16.h>
#include <cstdint>

#define BB 2
#define TT 2048
#define CC 1024
#define HH 16
#define DD 64
#define C3 3072
#define MROWS 4096   // BB*TT
#define NBH 32       // BB*HH

// ---------------- device global scratch ----------------
__device__ __align__(16) __half g_xh[MROWS * CC], g_xl[MROWS * CC];   // x split
__device__ __align__(16) __half g_wa[C3 * CC];                        // w_attn^T fp16 (q cols pre-scaled)
__device__ __align__(16) __half g_wp[CC * CC];                        // w_proj^T fp16
__device__ __align__(16) __half g_q[MROWS * CC];                      // q fp16 [b,t,h*d]
__device__ __align__(16) __half g_k[MROWS * CC];                      // k fp16
__device__ __align__(16) __half g_v[MROWS * CC];                      // v fp16
__device__ __align__(16) __half g_y[MROWS * CC];                      // attn out fp16

// ---------------- helpers ----------------
__device__ __forceinline__ uint32_t smem_u32(const void* p) {
    uint32_t a;
    asm("{ .reg .u64 t; cvta.to.shared.u64 t, %1; cvt.u32.u64 %0, t; }" : "=r"(a) : "l"(p));
    return a;
}
__device__ __forceinline__ void cp16(uint32_t s, const void* g) {
    asm volatile("cp.async.cg.shared.global [%0], [%1], 16;" :: "r"(s), "l"(g));
}
__device__ __forceinline__ void ldm_x4(uint32_t addr, uint32_t* r) {
    asm volatile("ldmatrix.sync.aligned.m8n8.x4.shared.b16 {%0,%1,%2,%3}, [%4];"
                 : "=r"(r[0]), "=r"(r[1]), "=r"(r[2]), "=r"(r[3]) : "r"(addr));
}
__device__ __forceinline__ void ldm_x4t(uint32_t addr, uint32_t* r) {
    asm volatile("ldmatrix.sync.aligned.m8n8.x4.trans.shared.b16 {%0,%1,%2,%3}, [%4];"
                 : "=r"(r[0]), "=r"(r[1]), "=r"(r[2]), "=r"(r[3]) : "r"(addr));
}
__device__ __forceinline__ void mma16816(float* c, const uint32_t* a, const uint32_t* b) {
    asm volatile("mma.sync.aligned.m16n8k16.row.col.f32.f16.f16.f32 "
                 "{%0,%1,%2,%3}, {%4,%5,%6,%7}, {%8,%9}, {%0,%1,%2,%3};"
                 : "+f"(c[0]), "+f"(c[1]), "+f"(c[2]), "+f"(c[3])
                 : "r"(a[0]), "r"(a[1]), "r"(a[2]), "r"(a[3]), "r"(b[0]), "r"(b[1]));
}
__device__ __forceinline__ void hsplit(float v, __half* h, __half* l) {
    __half hh = __float2half_rn(v);
    *h = hh;
    *l = __float2half_rn(v - __half2float(hh));
}
__device__ __forceinline__ uint32_t pack2h(float x, float y) {
    __half2 h = __floats2half2_rn(x, y);
    return *(uint32_t*)&h;
}

// ---------------- prep kernels ----------------
__global__ void __launch_bounds__(256) xprep_k(const float* __restrict__ x) {
    size_t i = ((size_t)blockIdx.x * 256 + threadIdx.x) * 4;
    float4 v = *(const float4*)(x + i);
    __half h[4], l[4];
    hsplit(v.x, &h[0], &l[0]);
    hsplit(v.y, &h[1], &l[1]);
    hsplit(v.z, &h[2], &l[2]);
    hsplit(v.w, &h[3], &l[3]);
    *(uint2*)(g_xh + i) = *(uint2*)h;
    *(uint2*)(g_xl + i) = *(uint2*)l;
}

// transpose w [CC][N] -> wt [N][CC] fp16; attn q-cols pre-scaled by (1/8)*log2(e)
__global__ void __launch_bounds__(256) wprep_k(const float* __restrict__ w, int N, int isattn) {
    __shared__ float ts[32][33];
    int tx = threadIdx.x & 31, ty = threadIdx.x >> 5;
    int n0 = blockIdx.x * 32, c0 = blockIdx.y * 32;
#pragma unroll
    for (int j = 0; j < 4; j++)
        ts[ty + j * 8][tx] = w[(size_t)(c0 + ty + j * 8) * N + n0 + tx];
    __syncthreads();
    __half* t = isattn ? g_wa : g_wp;
#pragma unroll
    for (int j = 0; j < 4; j++) {
        int n = n0 + ty + j * 8;
        float v = ts[tx][ty + j * 8];
        if (isattn && n < CC) v *= 0.18033688011112042f;  // (1/sqrt 64)*log2(e)
        t[(size_t)n * CC + c0 + tx] = __float2half_rn(v);
    }
}

// ---------------- mma.sync GEMM ----------------
// MODE 0: q  = x * w_attn^T[:,0:1024]     2-pass split-A -> g_q fp16
// MODE 1: kv = x * w_attn^T[:,1024:3072]  1-pass         -> g_k/g_v fp16
// MODE 3: out = y * w_proj^T              1-pass         -> fp32 out
template<int MODE>
__global__ void __launch_bounds__(256) gemm_mma(float* __restrict__ outp) {
    constexpr int NPASS = (MODE == 0) ? 2 : 1;
    constexpr int NTILE = 128;
    constexpr int NC  = 32;           // k chunks of 32
    constexpr int LDA = CC, LDB = CC;
    constexpr int WN  = NTILE / 2;
    constexpr int NN8 = WN / 8;
    constexpr int NJ  = WN / 16;
    constexpr int ASZ = 128 * 80;     // one 128x32 fp16 tile, 80B rows
    constexpr int STG = (NPASS + 1) * ASZ;  // [Ah,(Al),B]
    constexpr int NSTG = 3;

    extern __shared__ char sm[];
    const uint32_t smu = smem_u32(sm);
    const int tid = threadIdx.x, lane = tid & 31, wid = tid >> 5;
    const int wm = wid & 3, wn = wid >> 2;
    const int warpM = wm * 32, warpN = wn * WN;
    const int nt = blockIdx.x, mt = blockIdx.y;
    const int m0 = mt * 128, n0 = nt * NTILE;

    const __half *a_h, *a_l, *b_p;
    if constexpr (MODE == 0) {
        a_h = g_xh + (size_t)m0 * CC; a_l = g_xl + (size_t)m0 * CC;
        b_p = g_wa + (size_t)n0 * CC;                    // q columns
    } else if constexpr (MODE == 1) {
        a_h = g_xh + (size_t)m0 * CC; a_l = nullptr;
        b_p = g_wa + (size_t)(CC + n0) * CC;             // k,v columns
    } else {
        a_h = g_y + (size_t)m0 * CC;  a_l = nullptr;
        b_p = g_wp + (size_t)n0 * CC;
    }

    auto load_stage = [&](int st, int kc) {
        const uint32_t s0 = smu + st * STG;
        const int k0 = kc * 32;
#pragma unroll
        for (int i0 = 0; i0 < 128 * 4; i0 += 256) {
            int i = i0 + tid, r = i >> 2, c = i & 3;
            uint32_t sa = s0 + r * 80 + c * 16;
            cp16(sa, (const char*)(a_h + (size_t)r * LDA + k0) + c * 16);
            if constexpr (NPASS == 2)
                cp16(sa + ASZ, (const char*)(a_l + (size_t)r * LDA + k0) + c * 16);
            cp16(sa + NPASS * ASZ, (const char*)(b_p + (size_t)r * LDB + k0) + c * 16);
        }
        asm volatile("cp.async.commit_group;" ::: "memory");
    };

    const int grp = lane >> 3, r8 = lane & 7;
    const uint32_t aOff = (uint32_t)((warpM + r8 + (grp & 1) * 8) * 80 + (grp >> 1) * 16);
    const uint32_t bOff = (uint32_t)((warpN + r8 + (grp >> 1) * 8) * 80 + (grp & 1) * 16);

    float acc[2][NN8][4];
#pragma unroll
    for (int mi = 0; mi < 2; mi++)
#pragma unroll
        for (int ni = 0; ni < NN8; ni++)
#pragma unroll
            for (int e = 0; e < 4; e++) acc[mi][ni][e] = 0.f;

    load_stage(0, 0);
    load_stage(1, 1);

    int st = 0;
    for (int c = 0; c < NC; c++) {
        if (c + 2 < NC) { asm volatile("cp.async.wait_group 1;" ::: "memory"); }
        else            { asm volatile("cp.async.wait_group 0;" ::: "memory"); }
        __syncthreads();
        if (c + 2 < NC) {
            int st2 = st + 2; if (st2 >= NSTG) st2 -= NSTG;
            load_stage(st2, c + 2);
        }

        const uint32_t sA = smu + st * STG;
        const uint32_t sB = sA + NPASS * ASZ;
#pragma unroll
        for (int kk = 0; kk < 2; kk++) {
            const uint32_t kb = kk * 32;
            uint32_t aFh[2][4], aFl[2][4], bF[NJ][4];
            ldm_x4(sA + aOff + kb,           aFh[0]);
            ldm_x4(sA + aOff + 16 * 80 + kb, aFh[1]);
            if constexpr (NPASS == 2) {
                ldm_x4(sA + ASZ + aOff + kb,           aFl[0]);
                ldm_x4(sA + ASZ + aOff + 16 * 80 + kb, aFl[1]);
            }
#pragma unroll
            for (int nj = 0; nj < NJ; nj++)
                ldm_x4(sB + bOff + nj * 16 * 80 + kb, bF[nj]);
#pragma unroll
            for (int mi = 0; mi < 2; mi++)
#pragma unroll
                for (int ni = 0; ni < NN8; ni++)
                    mma16816(acc[mi][ni], aFh[mi], &bF[ni >> 1][(ni & 1) * 2]);
            if constexpr (NPASS == 2) {
#pragma unroll
                for (int mi = 0; mi < 2; mi++)
#pragma unroll
                    for (int ni = 0; ni < NN8; ni++)
                        mma16816(acc[mi][ni], aFl[mi], &bF[ni >> 1][(ni & 1) * 2]);
            }
        }
        if (++st == NSTG) st = 0;
    }

    const int row_l = lane >> 2, col_l = (lane & 3) * 2;
#pragma unroll
    for (int mi = 0; mi < 2; mi++) {
#pragma unroll
        for (int ni = 0; ni < NN8; ni++) {
            const int gr0 = m0 + warpM + mi * 16 + row_l;
            const int gc  = n0 + warpN + ni * 8 + col_l;
            const float* cc = acc[mi][ni];
            if constexpr (MODE == 0) {
                *(uint32_t*)(g_q + (size_t)gr0 * CC + gc)       = pack2h(cc[0], cc[1]);
                *(uint32_t*)(g_q + (size_t)(gr0 + 8) * CC + gc) = pack2h(cc[2], cc[3]);
            } else if constexpr (MODE == 1) {
                if (gc < CC) {
                    *(uint32_t*)(g_k + (size_t)gr0 * CC + gc)       = pack2h(cc[0], cc[1]);
                    *(uint32_t*)(g_k + (size_t)(gr0 + 8) * CC + gc) = pack2h(cc[2], cc[3]);
                } else {
                    *(uint32_t*)(g_v + (size_t)gr0 * CC + gc - CC)       = pack2h(cc[0], cc[1]);
                    *(uint32_t*)(g_v + (size_t)(gr0 + 8) * CC + gc - CC) = pack2h(cc[2], cc[3]);
                }
            } else {
                *(float2*)(outp + (size_t)gr0 * CC + gc)       = make_float2(cc[0], cc[1]);
                *(float2*)(outp + (size_t)(gr0 + 8) * CC + gc) = make_float2(cc[2], cc[3]);
            }
        }
    }
}

// ---------------- fused flash attention (fp16 single-pass, log2 domain) ----------------
__global__ void __launch_bounds__(256) flash_k() {
    constexpr int RSTR = 144;
    constexpr int BUF  = 64 * RSTR;   // one 64x64 fp16 tile
    constexpr int STG  = 2 * BUF;     // K, V
    constexpr int NSTG = 3;
    constexpr int NT   = TT / 64;

    extern __shared__ char sm[];
    const uint32_t smu = smem_u32(sm);
    const int tid = threadIdx.x, lane = tid & 31, wid = tid >> 5;
    const int qt = blockIdx.x, bh = blockIdx.y;
    const int b = bh >> 4, h = bh & 15;
    const int r = lane >> 2, cq = (lane & 3) * 2;

    // Q fragments straight from global, reused for all 32 key tiles
    const size_t qbase = ((size_t)b * TT + qt * 128 + wid * 16) * CC + h * DD;
    uint32_t qf[4][4];
#pragma unroll
    for (int kc = 0; kc < 4; kc++)
#pragma unroll
        for (int e = 0; e < 4; e++) {
            size_t off = qbase + (size_t)(r + (e & 1) * 8) * CC + kc * 16 + cq + (e >> 1) * 8;
            qf[kc][e] = *(const uint32_t*)(g_q + off);
        }

    float oacc[8][4];
#pragma unroll
    for (int nf = 0; nf < 8; nf++)
#pragma unroll
        for (int e = 0; e < 4; e++) oacc[nf][e] = 0.f;
    float m0r = -1e30f, m1r = -1e30f, l0r = 0.f, l1r = 0.f;

    const int grp = lane >> 3, r8 = lane & 7;
    const uint32_t kOff = (uint32_t)((r8 + (grp >> 1) * 8) * RSTR + (grp & 1) * 16);
    const uint32_t vOff = (uint32_t)(((grp & 1) * 8 + r8) * RSTR + (grp >> 1) * 16);
    const size_t kvb = (size_t)b * TT * CC + h * DD;

    auto load_tile = [&](int kt, int st) {
        const uint32_t s0 = smu + st * STG;
        const int t0 = kt * 64;
#pragma unroll
        for (int it = 0; it < 2; it++) {
            int i = it * 256 + tid;
            int rr = i >> 3, c = i & 7;
            uint32_t sa = s0 + rr * RSTR + c * 16;
            cp16(sa,       (const char*)(g_k + kvb + (size_t)(t0 + rr) * CC) + c * 16);
            cp16(sa + BUF, (const char*)(g_v + kvb + (size_t)(t0 + rr) * CC) + c * 16);
        }
        asm volatile("cp.async.commit_group;" ::: "memory");
    };

    load_tile(0, 0);
    load_tile(1, 1);

    int st = 0;
    for (int kt = 0; kt < NT; kt++) {
        if (kt + 2 < NT) { asm volatile("cp.async.wait_group 1;" ::: "memory"); }
        else             { asm volatile("cp.async.wait_group 0;" ::: "memory"); }
        __syncthreads();
        if (kt + 2 < NT) {
            int st2 = st + 2; if (st2 >= NSTG) st2 -= NSTG;
            load_tile(kt + 2, st2);
        }

        const uint32_t sK = smu + st * STG;
        const uint32_t sV = sK + BUF;

        // ---- S = Q K^T (single pass) ----
        float sacc[8][4];
#pragma unroll
        for (int nf = 0; nf < 8; nf++)
#pragma unroll
            for (int e = 0; e < 4; e++) sacc[nf][e] = 0.f;
#pragma unroll
        for (int kk = 0; kk < 4; kk++) {
            uint32_t bF[4][4];
#pragma unroll
            for (int nj = 0; nj < 4; nj++)
                ldm_x4(sK + kOff + nj * 16 * RSTR + kk * 32, bF[nj]);
#pragma unroll
            for (int nf = 0; nf < 8; nf++)
                mma16816(sacc[nf], qf[kk], &bF[nf >> 1][(nf & 1) * 2]);
        }

        // ---- online softmax (exp2 domain) ----
        float mx0 = -1e30f, mx1 = -1e30f;
#pragma unroll
        for (int nf = 0; nf < 8; nf++) {
            mx0 = fmaxf(mx0, fmaxf(sacc[nf][0], sacc[nf][1]));
            mx1 = fmaxf(mx1, fmaxf(sacc[nf][2], sacc[nf][3]));
        }
        mx0 = fmaxf(mx0, __shfl_xor_sync(0xffffffffu, mx0, 1));
        mx0 = fmaxf(mx0, __shfl_xor_sync(0xffffffffu, mx0, 2));
        mx1 = fmaxf(mx1, __shfl_xor_sync(0xffffffffu, mx1, 1));
        mx1 = fmaxf(mx1, __shfl_xor_sync(0xffffffffu, mx1, 2));
        const float mn0 = fmaxf(m0r, mx0), mn1 = fmaxf(m1r, mx1);
        const float al0 = exp2f(m0r - mn0), al1 = exp2f(m1r - mn1);
        float ls0 = 0.f, ls1 = 0.f;
#pragma unroll
        for (int nf = 0; nf < 8; nf++) {
            sacc[nf][0] = exp2f(sacc[nf][0] - mn0);
            sacc[nf][1] = exp2f(sacc[nf][1] - mn0);
            sacc[nf][2] = exp2f(sacc[nf][2] - mn1);
            sacc[nf][3] = exp2f(sacc[nf][3] - mn1);
            ls0 += sacc[nf][0] + sacc[nf][1];
            ls1 += sacc[nf][2] + sacc[nf][3];
        }
        ls0 += __shfl_xor_sync(0xffffffffu, ls0, 1);
        ls0 += __shfl_xor_sync(0xffffffffu, ls0, 2);
        ls1 += __shfl_xor_sync(0xffffffffu, ls1, 1);
        ls1 += __shfl_xor_sync(0xffffffffu, ls1, 2);
        l0r = l0r * al0 + ls0; m0r = mn0;
        l1r = l1r * al1 + ls1; m1r = mn1;
#pragma unroll
        for (int nf = 0; nf < 8; nf++) {
            oacc[nf][0] *= al0; oacc[nf][1] *= al0;
            oacc[nf][2] *= al1; oacc[nf][3] *= al1;
        }

        // ---- P -> fp16 A-fragments (accumulator layout identity) ----
        uint32_t pf[4][4];
#pragma unroll
        for (int kc = 0; kc < 4; kc++) {
            pf[kc][0] = pack2h(sacc[2 * kc][0],     sacc[2 * kc][1]);
            pf[kc][1] = pack2h(sacc[2 * kc][2],     sacc[2 * kc][3]);
            pf[kc][2] = pack2h(sacc[2 * kc + 1][0], sacc[2 * kc + 1][1]);
            pf[kc][3] = pack2h(sacc[2 * kc + 1][2], sacc[2 * kc + 1][3]);
        }

        // ---- O += P V (single pass), V via ldmatrix.trans ----
#pragma unroll
        for (int kc = 0; kc < 4; kc++) {
            uint32_t vF[4][4];
#pragma unroll
            for (int db = 0; db < 4; db++)
                ldm_x4t(sV + kc * 16 * RSTR + vOff + db * 32, vF[db]);
#pragma unroll
            for (int nf = 0; nf < 8; nf++)
                mma16816(oacc[nf], pf[kc], &vF[nf >> 1][(nf & 1) * 2]);
        }
        if (++st == NSTG) st = 0;
    }

    const float inv0 = 1.f / l0r, inv1 = 1.f / l1r;
    const size_t yb = ((size_t)b * TT + qt * 128 + wid * 16) * CC + h * DD;
#pragma unroll
    for (int nf = 0; nf < 8; nf++) {
        const int col = nf * 8 + cq;
        *(uint32_t*)(g_y + yb + (size_t)r * CC + col) =
            pack2h(oacc[nf][0] * inv0, oacc[nf][1] * inv0);
        *(uint32_t*)(g_y + yb + (size_t)(r + 8) * CC + col) =
            pack2h(oacc[nf][2] * inv1, oacc[nf][3] * inv1);
    }
}

// ---------------- host launcher ----------------
extern "C" void kernel_launch(void* const* d_in, const int* in_sizes, int n_in,
                              void* d_out, int out_size) {
    const float* x  = (const float*)d_in[0];
    const float* wa = (const float*)d_in[1];
    const float* wp = (const float*)d_in[2];
    float* out = (float*)d_out;

    constexpr int SM_Q     = 3 * 3 * 128 * 80;   // 92160 (3 stages x [Ah,Al,B])
    constexpr int SM_1P    = 3 * 2 * 128 * 80;   // 61440 (3 stages x [A,B])
    constexpr int SM_FLASH = 3 * 2 * 64 * 144;   // 55296 (3 stages x [K,V])

    cudaFuncSetAttribute((const void*)gemm_mma<0>, cudaFuncAttributeMaxDynamicSharedMemorySize, SM_Q);
    cudaFuncSetAttribute((const void*)gemm_mma<1>, cudaFuncAttributeMaxDynamicSharedMemorySize, SM_1P);
    cudaFuncSetAttribute((const void*)gemm_mma<3>, cudaFuncAttributeMaxDynamicSharedMemorySize, SM_1P);
    cudaFuncSetAttribute((const void*)flash_k,     cudaFuncAttributeMaxDynamicSharedMemorySize, SM_FLASH);

    xprep_k<<<MROWS * CC / 1024, 256>>>(x);
    wprep_k<<<dim3(C3 / 32, CC / 32), 256>>>(wa, C3, 1);
    wprep_k<<<dim3(CC / 32, CC / 32), 256>>>(wp, CC, 0);

    gemm_mma<0><<<dim3(CC / 128, MROWS / 128), 256, SM_Q>>>(nullptr);        // q (2-pass)
    gemm_mma<1><<<dim3(2 * CC / 128, MROWS / 128), 256, SM_1P>>>(nullptr);   // k,v (1-pass)
    flash_k<<<dim3(TT / 128, NBH), 256, SM_FLASH>>>();                       // fused attention
    gemm_mma<3><<<dim3(CC / 128, MROWS / 128), 256, SM_1P>>>(out);           // proj
}

// round 10
// speedup vs baseline: 13.3232x; 1.0933x over previous
#include <cuda_runtime.h>
#include <cuda_fp16.h>
#include <cstdint>

#define BB 2
#define TT 2048
#define CC 1024
#define HH 16
#define DD 64
#define C3 3072
#define MROWS 4096   // BB*TT
#define NBH 32       // BB*HH

// ---------------- device global scratch ----------------
__device__ __align__(16) __half g_x[MROWS * CC];     // x fp16
__device__ __align__(16) __half g_wa[C3 * CC];       // w_attn^T fp16 (q cols pre-scaled)
__device__ __align__(16) __half g_wp[CC * CC];       // w_proj^T fp16
__device__ __align__(16) __half g_q[MROWS * CC];     // q fp16 [b,t,h*d]
__device__ __align__(16) __half g_k[MROWS * CC];     // k fp16
__device__ __align__(16) __half g_v[MROWS * CC];     // v fp16
__device__ __align__(16) __half g_y[MROWS * CC];     // attn out fp16

// ---------------- helpers ----------------
__device__ __forceinline__ uint32_t smem_u32(const void* p) {
    uint32_t a;
    asm("{ .reg .u64 t; cvta.to.shared.u64 t, %1; cvt.u32.u64 %0, t; }" : "=r"(a) : "l"(p));
    return a;
}
__device__ __forceinline__ void cp16(uint32_t s, const void* g) {
    asm volatile("cp.async.cg.shared.global [%0], [%1], 16;" :: "r"(s), "l"(g));
}
__device__ __forceinline__ void ldm_x4(uint32_t addr, uint32_t* r) {
    asm volatile("ldmatrix.sync.aligned.m8n8.x4.shared.b16 {%0,%1,%2,%3}, [%4];"
                 : "=r"(r[0]), "=r"(r[1]), "=r"(r[2]), "=r"(r[3]) : "r"(addr));
}
__device__ __forceinline__ void ldm_x4t(uint32_t addr, uint32_t* r) {
    asm volatile("ldmatrix.sync.aligned.m8n8.x4.trans.shared.b16 {%0,%1,%2,%3}, [%4];"
                 : "=r"(r[0]), "=r"(r[1]), "=r"(r[2]), "=r"(r[3]) : "r"(addr));
}
__device__ __forceinline__ void mma16816(float* c, const uint32_t* a, const uint32_t* b) {
    asm volatile("mma.sync.aligned.m16n8k16.row.col.f32.f16.f16.f32 "
                 "{%0,%1,%2,%3}, {%4,%5,%6,%7}, {%8,%9}, {%0,%1,%2,%3};"
                 : "+f"(c[0]), "+f"(c[1]), "+f"(c[2]), "+f"(c[3])
                 : "r"(a[0]), "r"(a[1]), "r"(a[2]), "r"(a[3]), "r"(b[0]), "r"(b[1]));
}
__device__ __forceinline__ uint32_t pack2h(float x, float y) {
    __half2 h = __floats2half2_rn(x, y);
    return *(uint32_t*)&h;
}

// ---------------- prep kernels ----------------
__global__ void __launch_bounds__(256) xprep_k(const float* __restrict__ x) {
    size_t i = ((size_t)blockIdx.x * 256 + threadIdx.x) * 4;
    float4 v = *(const float4*)(x + i);
    __half h[4] = {__float2half_rn(v.x), __float2half_rn(v.y),
                   __float2half_rn(v.z), __float2half_rn(v.w)};
    *(uint2*)(g_x + i) = *(uint2*)h;
}

// transpose w [CC][N] -> wt [N][CC] fp16; attn q-cols pre-scaled by (1/8)*log2(e)
__global__ void __launch_bounds__(256) wprep_k(const float* __restrict__ w, int N, int isattn) {
    __shared__ float ts[32][33];
    int tx = threadIdx.x & 31, ty = threadIdx.x >> 5;
    int n0 = blockIdx.x * 32, c0 = blockIdx.y * 32;
#pragma unroll
    for (int j = 0; j < 4; j++)
        ts[ty + j * 8][tx] = w[(size_t)(c0 + ty + j * 8) * N + n0 + tx];
    __syncthreads();
    __half* t = isattn ? g_wa : g_wp;
#pragma unroll
    for (int j = 0; j < 4; j++) {
        int n = n0 + ty + j * 8;
        float v = ts[tx][ty + j * 8];
        if (isattn && n < CC) v *= 0.18033688011112042f;  // (1/sqrt 64)*log2(e)
        t[(size_t)n * CC + c0 + tx] = __float2half_rn(v);
    }
}

// ---------------- mma.sync GEMM (1-pass fp16) ----------------
// MODE 0: qkv = x * w_attn^T  -> g_q/g_k/g_v fp16   M=4096 N=3072 K=1024
// MODE 1: out = y * w_proj^T  -> fp32 out           M=4096 N=1024 K=1024
template<int MODE>
__global__ void __launch_bounds__(256) gemm_mma(float* __restrict__ outp) {
    constexpr int NTILE = 128;
    constexpr int NC  = 32;           // k chunks of 32
    constexpr int LDA = CC, LDB = CC;
    constexpr int WN  = NTILE / 2;
    constexpr int NN8 = WN / 8;
    constexpr int NJ  = WN / 16;
    constexpr int ASZ = 128 * 80;     // one 128x32 fp16 tile, 80B rows
    constexpr int STG = 2 * ASZ;      // [A,B]
    constexpr int NSTG = 3;

    extern __shared__ char sm[];
    const uint32_t smu = smem_u32(sm);
    const int tid = threadIdx.x, lane = tid & 31, wid = tid >> 5;
    const int wm = wid & 3, wn = wid >> 2;
    const int warpM = wm * 32, warpN = wn * WN;
    const int nt = blockIdx.x, mt = blockIdx.y;
    const int m0 = mt * 128, n0 = nt * NTILE;

    const __half *a_p, *b_p;
    if constexpr (MODE == 0) {
        a_p = g_x + (size_t)m0 * CC;
        b_p = g_wa + (size_t)n0 * CC;
    } else {
        a_p = g_y + (size_t)m0 * CC;
        b_p = g_wp + (size_t)n0 * CC;
    }

    auto load_stage = [&](int st, int kc) {
        const uint32_t s0 = smu + st * STG;
        const int k0 = kc * 32;
#pragma unroll
        for (int i0 = 0; i0 < 128 * 4; i0 += 256) {
            int i = i0 + tid, r = i >> 2, c = i & 3;
            uint32_t sa = s0 + r * 80 + c * 16;
            cp16(sa,       (const char*)(a_p + (size_t)r * LDA + k0) + c * 16);
            cp16(sa + ASZ, (const char*)(b_p + (size_t)r * LDB + k0) + c * 16);
        }
        asm volatile("cp.async.commit_group;" ::: "memory");
    };

    const int grp = lane >> 3, r8 = lane & 7;
    const uint32_t aOff = (uint32_t)((warpM + r8 + (grp & 1) * 8) * 80 + (grp >> 1) * 16);
    const uint32_t bOff = (uint32_t)((warpN + r8 + (grp >> 1) * 8) * 80 + (grp & 1) * 16);

    float acc[2][NN8][4];
#pragma unroll
    for (int mi = 0; mi < 2; mi++)
#pragma unroll
        for (int ni = 0; ni < NN8; ni++)
#pragma unroll
            for (int e = 0; e < 4; e++) acc[mi][ni][e] = 0.f;

    load_stage(0, 0);
    load_stage(1, 1);

    int st = 0;
    for (int c = 0; c < NC; c++) {
        if (c + 2 < NC) { asm volatile("cp.async.wait_group 1;" ::: "memory"); }
        else            { asm volatile("cp.async.wait_group 0;" ::: "memory"); }
        __syncthreads();
        if (c + 2 < NC) {
            int st2 = st + 2; if (st2 >= NSTG) st2 -= NSTG;
            load_stage(st2, c + 2);
        }

        const uint32_t sA = smu + st * STG;
        const uint32_t sB = sA + ASZ;
#pragma unroll
        for (int kk = 0; kk < 2; kk++) {
            const uint32_t kb = kk * 32;
            uint32_t aF[2][4], bF[NJ][4];
            ldm_x4(sA + aOff + kb,           aF[0]);
            ldm_x4(sA + aOff + 16 * 80 + kb, aF[1]);
#pragma unroll
            for (int nj = 0; nj < NJ; nj++)
                ldm_x4(sB + bOff + nj * 16 * 80 + kb, bF[nj]);
#pragma unroll
            for (int mi = 0; mi < 2; mi++)
#pragma unroll
                for (int ni = 0; ni < NN8; ni++)
                    mma16816(acc[mi][ni], aF[mi], &bF[ni >> 1][(ni & 1) * 2]);
        }
        if (++st == NSTG) st = 0;
    }

    const int row_l = lane >> 2, col_l = (lane & 3) * 2;
#pragma unroll
    for (int mi = 0; mi < 2; mi++) {
#pragma unroll
        for (int ni = 0; ni < NN8; ni++) {
            const int gr0 = m0 + warpM + mi * 16 + row_l;
            const int gc  = n0 + warpN + ni * 8 + col_l;
            const float* cc = acc[mi][ni];
            if constexpr (MODE == 0) {
                __half* dst;
                int gcl;
                if (gc < CC)           { dst = g_q; gcl = gc; }
                else if (gc < 2 * CC)  { dst = g_k; gcl = gc - CC; }
                else                   { dst = g_v; gcl = gc - 2 * CC; }
                *(uint32_t*)(dst + (size_t)gr0 * CC + gcl)       = pack2h(cc[0], cc[1]);
                *(uint32_t*)(dst + (size_t)(gr0 + 8) * CC + gcl) = pack2h(cc[2], cc[3]);
            } else {
                *(float2*)(outp + (size_t)gr0 * CC + gc)       = make_float2(cc[0], cc[1]);
                *(float2*)(outp + (size_t)(gr0 + 8) * CC + gc) = make_float2(cc[2], cc[3]);
            }
        }
    }
}

// ---------------- fused flash attention (fp16 single-pass, log2 domain) ----------------
__global__ void __launch_bounds__(256) flash_k() {
    constexpr int RSTR = 144;
    constexpr int BUF  = 64 * RSTR;   // one 64x64 fp16 tile
    constexpr int STG  = 2 * BUF;     // K, V
    constexpr int NSTG = 3;
    constexpr int NT   = TT / 64;

    extern __shared__ char sm[];
    const uint32_t smu = smem_u32(sm);
    const int tid = threadIdx.x, lane = tid & 31, wid = tid >> 5;
    const int qt = blockIdx.x, bh = blockIdx.y;
    const int b = bh >> 4, h = bh & 15;
    const int r = lane >> 2, cq = (lane & 3) * 2;

    // Q fragments straight from global, reused for all 32 key tiles
    const size_t qbase = ((size_t)b * TT + qt * 128 + wid * 16) * CC + h * DD;
    uint32_t qf[4][4];
#pragma unroll
    for (int kc = 0; kc < 4; kc++)
#pragma unroll
        for (int e = 0; e < 4; e++) {
            size_t off = qbase + (size_t)(r + (e & 1) * 8) * CC + kc * 16 + cq + (e >> 1) * 8;
            qf[kc][e] = *(const uint32_t*)(g_q + off);
        }

    float oacc[8][4];
#pragma unroll
    for (int nf = 0; nf < 8; nf++)
#pragma unroll
        for (int e = 0; e < 4; e++) oacc[nf][e] = 0.f;
    float m0r = -1e30f, m1r = -1e30f, l0r = 0.f, l1r = 0.f;

    const int grp = lane >> 3, r8 = lane & 7;
    const uint32_t kOff = (uint32_t)((r8 + (grp >> 1) * 8) * RSTR + (grp & 1) * 16);
    const uint32_t vOff = (uint32_t)(((grp & 1) * 8 + r8) * RSTR + (grp >> 1) * 16);
    const size_t kvb = (size_t)b * TT * CC + h * DD;

    auto load_tile = [&](int kt, int st) {
        const uint32_t s0 = smu + st * STG;
        const int t0 = kt * 64;
#pragma unroll
        for (int it = 0; it < 2; it++) {
            int i = it * 256 + tid;
            int rr = i >> 3, c = i & 7;
            uint32_t sa = s0 + rr * RSTR + c * 16;
            cp16(sa,       (const char*)(g_k + kvb + (size_t)(t0 + rr) * CC) + c * 16);
            cp16(sa + BUF, (const char*)(g_v + kvb + (size_t)(t0 + rr) * CC) + c * 16);
        }
        asm volatile("cp.async.commit_group;" ::: "memory");
    };

    load_tile(0, 0);
    load_tile(1, 1);

    int st = 0;
    for (int kt = 0; kt < NT; kt++) {
        if (kt + 2 < NT) { asm volatile("cp.async.wait_group 1;" ::: "memory"); }
        else             { asm volatile("cp.async.wait_group 0;" ::: "memory"); }
        __syncthreads();
        if (kt + 2 < NT) {
            int st2 = st + 2; if (st2 >= NSTG) st2 -= NSTG;
            load_tile(kt + 2, st2);
        }

        const uint32_t sK = smu + st * STG;
        const uint32_t sV = sK + BUF;

        // ---- S = Q K^T (single pass) ----
        float sacc[8][4];
#pragma unroll
        for (int nf = 0; nf < 8; nf++)
#pragma unroll
            for (int e = 0; e < 4; e++) sacc[nf][e] = 0.f;
#pragma unroll
        for (int kk = 0; kk < 4; kk++) {
            uint32_t bF[4][4];
#pragma unroll
            for (int nj = 0; nj < 4; nj++)
                ldm_x4(sK + kOff + nj * 16 * RSTR + kk * 32, bF[nj]);
#pragma unroll
            for (int nf = 0; nf < 8; nf++)
                mma16816(sacc[nf], qf[kk], &bF[nf >> 1][(nf & 1) * 2]);
        }

        // ---- online softmax (exp2 domain) ----
        float mx0 = -1e30f, mx1 = -1e30f;
#pragma unroll
        for (int nf = 0; nf < 8; nf++) {
            mx0 = fmaxf(mx0, fmaxf(sacc[nf][0], sacc[nf][1]));
            mx1 = fmaxf(mx1, fmaxf(sacc[nf][2], sacc[nf][3]));
        }
        mx0 = fmaxf(mx0, __shfl_xor_sync(0xffffffffu, mx0, 1));
        mx0 = fmaxf(mx0, __shfl_xor_sync(0xffffffffu, mx0, 2));
        mx1 = fmaxf(mx1, __shfl_xor_sync(0xffffffffu, mx1, 1));
        mx1 = fmaxf(mx1, __shfl_xor_sync(0xffffffffu, mx1, 2));
        const float mn0 = fmaxf(m0r, mx0), mn1 = fmaxf(m1r, mx1);
        const float al0 = exp2f(m0r - mn0), al1 = exp2f(m1r - mn1);
        float ls0 = 0.f, ls1 = 0.f;
#pragma unroll
        for (int nf = 0; nf < 8; nf++) {
            sacc[nf][0] = exp2f(sacc[nf][0] - mn0);
            sacc[nf][1] = exp2f(sacc[nf][1] - mn0);
            sacc[nf][2] = exp2f(sacc[nf][2] - mn1);
            sacc[nf][3] = exp2f(sacc[nf][3] - mn1);
            ls0 += sacc[nf][0] + sacc[nf][1];
            ls1 += sacc[nf][2] + sacc[nf][3];
        }
        ls0 += __shfl_xor_sync(0xffffffffu, ls0, 1);
        ls0 += __shfl_xor_sync(0xffffffffu, ls0, 2);
        ls1 += __shfl_xor_sync(0xffffffffu, ls1, 1);
        ls1 += __shfl_xor_sync(0xffffffffu, ls1, 2);
        l0r = l0r * al0 + ls0; m0r = mn0;
        l1r = l1r * al1 + ls1; m1r = mn1;
#pragma unroll
        for (int nf = 0; nf < 8; nf++) {
            oacc[nf][0] *= al0; oacc[nf][1] *= al0;
            oacc[nf][2] *= al1; oacc[nf][3] *= al1;
        }

        // ---- P -> fp16 A-fragments (accumulator layout identity) ----
        uint32_t pf[4][4];
#pragma unroll
        for (int kc = 0; kc < 4; kc++) {
            pf[kc][0] = pack2h(sacc[2 * kc][0],     sacc[2 * kc][1]);
            pf[kc][1] = pack2h(sacc[2 * kc][2],     sacc[2 * kc][3]);
            pf[kc][2] = pack2h(sacc[2 * kc + 1][0], sacc[2 * kc + 1][1]);
            pf[kc][3] = pack2h(sacc[2 * kc + 1][2], sacc[2 * kc + 1][3]);
        }

        // ---- O += P V (single pass), V via ldmatrix.trans ----
#pragma unroll
        for (int kc = 0; kc < 4; kc++) {
            uint32_t vF[4][4];
#pragma unroll
            for (int db = 0; db < 4; db++)
                ldm_x4t(sV + kc * 16 * RSTR + vOff + db * 32, vF[db]);
#pragma unroll
            for (int nf = 0; nf < 8; nf++)
                mma16816(oacc[nf], pf[kc], &vF[nf >> 1][(nf & 1) * 2]);
        }
        if (++st == NSTG) st = 0;
    }

    const float inv0 = 1.f / l0r, inv1 = 1.f / l1r;
    const size_t yb = ((size_t)b * TT + qt * 128 + wid * 16) * CC + h * DD;
#pragma unroll
    for (int nf = 0; nf < 8; nf++) {
        const int col = nf * 8 + cq;
        *(uint32_t*)(g_y + yb + (size_t)r * CC + col) =
            pack2h(oacc[nf][0] * inv0, oacc[nf][1] * inv0);
        *(uint32_t*)(g_y + yb + (size_t)(r + 8) * CC + col) =
            pack2h(oacc[nf][2] * inv1, oacc[nf][3] * inv1);
    }
}

// ---------------- host launcher ----------------
extern "C" void kernel_launch(void* const* d_in, const int* in_sizes, int n_in,
                              void* d_out, int out_size) {
    const float* x  = (const float*)d_in[0];
    const float* wa = (const float*)d_in[1];
    const float* wp = (const float*)d_in[2];
    float* out = (float*)d_out;

    constexpr int SM_GEMM  = 3 * 2 * 128 * 80;   // 61440 (3 stages x [A,B])
    constexpr int SM_FLASH = 3 * 2 * 64 * 144;   // 55296 (3 stages x [K,V])

    cudaFuncSetAttribute((const void*)gemm_mma<0>, cudaFuncAttributeMaxDynamicSharedMemorySize, SM_GEMM);
    cudaFuncSetAttribute((const void*)gemm_mma<1>, cudaFuncAttributeMaxDynamicSharedMemorySize, SM_GEMM);
    cudaFuncSetAttribute((const void*)flash_k,     cudaFuncAttributeMaxDynamicSharedMemorySize, SM_FLASH);

    xprep_k<<<MROWS * CC / 1024, 256>>>(x);
    wprep_k<<<dim3(C3 / 32, CC / 32), 256>>>(wa, C3, 1);
    wprep_k<<<dim3(CC / 32, CC / 32), 256>>>(wp, CC, 0);

    gemm_mma<0><<<dim3(C3 / 128, MROWS / 128), 256, SM_GEMM>>>(nullptr);  // qkv (1-pass)
    flash_k<<<dim3(TT / 128, NBH), 256, SM_FLASH>>>();                    // fused attention
    gemm_mma<1><<<dim3(CC / 128, MROWS / 128), 256, SM_GEMM>>>(out);      // proj (1-pass)
}

// round 11
// speedup vs baseline: 14.2796x; 1.0718x over previous
#include <cuda_runtime.h>
#include <cuda_fp16.h>
#include <cstdint>

#define BB 2
#define TT 2048
#define CC 1024
#define HH 16
#define DD 64
#define C3 3072
#define MROWS 4096   // BB*TT
#define NBH 32       // BB*HH

// ---------------- device global scratch ----------------
__device__ __align__(16) __half g_x[MROWS * CC];     // x fp16
__device__ __align__(16) __half g_wa[C3 * CC];       // w_attn^T fp16 (q cols pre-scaled)
__device__ __align__(16) __half g_wp[CC * CC];       // w_proj^T fp16
__device__ __align__(16) __half g_q[MROWS * CC];     // q fp16 [b,t,h*d]
__device__ __align__(16) __half g_k[MROWS * CC];     // k fp16
__device__ __align__(16) __half g_v[MROWS * CC];     // v fp16
__device__ __align__(16) __half g_y[MROWS * CC];     // attn out fp16

// ---------------- helpers ----------------
__device__ __forceinline__ uint32_t smem_u32(const void* p) {
    uint32_t a;
    asm("{ .reg .u64 t; cvta.to.shared.u64 t, %1; cvt.u32.u64 %0, t; }" : "=r"(a) : "l"(p));
    return a;
}
__device__ __forceinline__ void cp16(uint32_t s, const void* g) {
    asm volatile("cp.async.cg.shared.global [%0], [%1], 16;" :: "r"(s), "l"(g));
}
__device__ __forceinline__ void ldm_x4(uint32_t addr, uint32_t* r) {
    asm volatile("ldmatrix.sync.aligned.m8n8.x4.shared.b16 {%0,%1,%2,%3}, [%4];"
                 : "=r"(r[0]), "=r"(r[1]), "=r"(r[2]), "=r"(r[3]) : "r"(addr));
}
__device__ __forceinline__ void ldm_x4t(uint32_t addr, uint32_t* r) {
    asm volatile("ldmatrix.sync.aligned.m8n8.x4.trans.shared.b16 {%0,%1,%2,%3}, [%4];"
                 : "=r"(r[0]), "=r"(r[1]), "=r"(r[2]), "=r"(r[3]) : "r"(addr));
}
__device__ __forceinline__ void mma16816(float* c, const uint32_t* a, const uint32_t* b) {
    asm volatile("mma.sync.aligned.m16n8k16.row.col.f32.f16.f16.f32 "
                 "{%0,%1,%2,%3}, {%4,%5,%6,%7}, {%8,%9}, {%0,%1,%2,%3};"
                 : "+f"(c[0]), "+f"(c[1]), "+f"(c[2]), "+f"(c[3])
                 : "r"(a[0]), "r"(a[1]), "r"(a[2]), "r"(a[3]), "r"(b[0]), "r"(b[1]));
}
__device__ __forceinline__ uint32_t pack2h(float x, float y) {
    __half2 h = __floats2half2_rn(x, y);
    return *(uint32_t*)&h;
}
__device__ __forceinline__ float ex2(float x) {
    float y;
    asm("ex2.approx.ftz.f32 %0, %1;" : "=f"(y) : "f"(x));
    return y;
}

// ---------------- prep kernels ----------------
__global__ void __launch_bounds__(256) xprep_k(const float* __restrict__ x) {
    size_t i = ((size_t)blockIdx.x * 256 + threadIdx.x) * 4;
    float4 v = *(const float4*)(x + i);
    __half h[4] = {__float2half_rn(v.x), __float2half_rn(v.y),
                   __float2half_rn(v.z), __float2half_rn(v.w)};
    *(uint2*)(g_x + i) = *(uint2*)h;
}

// transpose w [CC][N] -> wt [N][CC] fp16; attn q-cols pre-scaled by (1/8)*log2(e)
__global__ void __launch_bounds__(256) wprep_k(const float* __restrict__ w, int N, int isattn) {
    __shared__ float ts[32][33];
    int tx = threadIdx.x & 31, ty = threadIdx.x >> 5;
    int n0 = blockIdx.x * 32, c0 = blockIdx.y * 32;
#pragma unroll
    for (int j = 0; j < 4; j++)
        ts[ty + j * 8][tx] = w[(size_t)(c0 + ty + j * 8) * N + n0 + tx];
    __syncthreads();
    __half* t = isattn ? g_wa : g_wp;
#pragma unroll
    for (int j = 0; j < 4; j++) {
        int n = n0 + ty + j * 8;
        float v = ts[tx][ty + j * 8];
        if (isattn && n < CC) v *= 0.18033688011112042f;  // (1/sqrt 64)*log2(e)
        t[(size_t)n * CC + c0 + tx] = __float2half_rn(v);
    }
}

// ---------------- mma.sync GEMM (1-pass fp16, batched fragment loads) ----------------
// MODE 0: qkv = x * w_attn^T  -> g_q/g_k/g_v fp16   M=4096 N=3072 K=1024
// MODE 1: out = y * w_proj^T  -> fp32 out           M=4096 N=1024 K=1024
template<int MODE>
__global__ void __launch_bounds__(256, 2) gemm_mma(float* __restrict__ outp) {
    constexpr int NTILE = 128;
    constexpr int NC  = 32;           // k chunks of 32
    constexpr int LDA = CC, LDB = CC;
    constexpr int WN  = NTILE / 2;
    constexpr int NN8 = WN / 8;
    constexpr int NJ  = WN / 16;
    constexpr int ASZ = 128 * 80;     // one 128x32 fp16 tile, 80B rows
    constexpr int STG = 2 * ASZ;      // [A,B]
    constexpr int NSTG = 3;

    extern __shared__ char sm[];
    const uint32_t smu = smem_u32(sm);
    const int tid = threadIdx.x, lane = tid & 31, wid = tid >> 5;
    const int wm = wid & 3, wn = wid >> 2;
    const int warpM = wm * 32, warpN = wn * WN;
    const int nt = blockIdx.x, mt = blockIdx.y;
    const int m0 = mt * 128, n0 = nt * NTILE;

    const __half *a_p, *b_p;
    if constexpr (MODE == 0) {
        a_p = g_x + (size_t)m0 * CC;
        b_p = g_wa + (size_t)n0 * CC;
    } else {
        a_p = g_y + (size_t)m0 * CC;
        b_p = g_wp + (size_t)n0 * CC;
    }

    auto load_stage = [&](int st, int kc) {
        const uint32_t s0 = smu + st * STG;
        const int k0 = kc * 32;
#pragma unroll
        for (int i0 = 0; i0 < 128 * 4; i0 += 256) {
            int i = i0 + tid, r = i >> 2, c = i & 3;
            uint32_t sa = s0 + r * 80 + c * 16;
            cp16(sa,       (const char*)(a_p + (size_t)r * LDA + k0) + c * 16);
            cp16(sa + ASZ, (const char*)(b_p + (size_t)r * LDB + k0) + c * 16);
        }
        asm volatile("cp.async.commit_group;" ::: "memory");
    };

    const int grp = lane >> 3, r8 = lane & 7;
    const uint32_t aOff = (uint32_t)((warpM + r8 + (grp & 1) * 8) * 80 + (grp >> 1) * 16);
    const uint32_t bOff = (uint32_t)((warpN + r8 + (grp >> 1) * 8) * 80 + (grp & 1) * 16);

    float acc[2][NN8][4];
#pragma unroll
    for (int mi = 0; mi < 2; mi++)
#pragma unroll
        for (int ni = 0; ni < NN8; ni++)
#pragma unroll
            for (int e = 0; e < 4; e++) acc[mi][ni][e] = 0.f;

    load_stage(0, 0);
    load_stage(1, 1);

    int st = 0;
    for (int c = 0; c < NC; c++) {
        if (c + 2 < NC) { asm volatile("cp.async.wait_group 1;" ::: "memory"); }
        else            { asm volatile("cp.async.wait_group 0;" ::: "memory"); }
        __syncthreads();
        if (c + 2 < NC) {
            int st2 = st + 2; if (st2 >= NSTG) st2 -= NSTG;
            load_stage(st2, c + 2);
        }

        const uint32_t sA = smu + st * STG;
        const uint32_t sB = sA + ASZ;
        // batch ALL fragment loads for both kk steps (12 independent LDSM),
        // then all 32 MMAs -> hides LDSM latency inside the warp
        uint32_t aF[2][2][4], bF[2][NJ][4];
#pragma unroll
        for (int kk = 0; kk < 2; kk++) {
            const uint32_t kb = kk * 32;
            ldm_x4(sA + aOff + kb,           aF[kk][0]);
            ldm_x4(sA + aOff + 16 * 80 + kb, aF[kk][1]);
#pragma unroll
            for (int nj = 0; nj < NJ; nj++)
                ldm_x4(sB + bOff + nj * 16 * 80 + kb, bF[kk][nj]);
        }
#pragma unroll
        for (int kk = 0; kk < 2; kk++)
#pragma unroll
            for (int mi = 0; mi < 2; mi++)
#pragma unroll
                for (int ni = 0; ni < NN8; ni++)
                    mma16816(acc[mi][ni], aF[kk][mi], &bF[kk][ni >> 1][(ni & 1) * 2]);
        if (++st == NSTG) st = 0;
    }

    const int row_l = lane >> 2, col_l = (lane & 3) * 2;
#pragma unroll
    for (int mi = 0; mi < 2; mi++) {
#pragma unroll
        for (int ni = 0; ni < NN8; ni++) {
            const int gr0 = m0 + warpM + mi * 16 + row_l;
            const int gc  = n0 + warpN + ni * 8 + col_l;
            const float* cc = acc[mi][ni];
            if constexpr (MODE == 0) {
                __half* dst;
                int gcl;
                if (gc < CC)           { dst = g_q; gcl = gc; }
                else if (gc < 2 * CC)  { dst = g_k; gcl = gc - CC; }
                else                   { dst = g_v; gcl = gc - 2 * CC; }
                *(uint32_t*)(dst + (size_t)gr0 * CC + gcl)       = pack2h(cc[0], cc[1]);
                *(uint32_t*)(dst + (size_t)(gr0 + 8) * CC + gcl) = pack2h(cc[2], cc[3]);
            } else {
                *(float2*)(outp + (size_t)gr0 * CC + gc)       = make_float2(cc[0], cc[1]);
                *(float2*)(outp + (size_t)(gr0 + 8) * CC + gc) = make_float2(cc[2], cc[3]);
            }
        }
    }
}

// ---------------- fused flash attention (fp16 single-pass, log2 domain) ----------------
__global__ void __launch_bounds__(256) flash_k() {
    constexpr int RSTR = 144;
    constexpr int BUF  = 64 * RSTR;   // one 64x64 fp16 tile
    constexpr int STG  = 2 * BUF;     // K, V
    constexpr int NSTG = 3;
    constexpr int NT   = TT / 64;

    extern __shared__ char sm[];
    const uint32_t smu = smem_u32(sm);
    const int tid = threadIdx.x, lane = tid & 31, wid = tid >> 5;
    const int qt = blockIdx.x, bh = blockIdx.y;
    const int b = bh >> 4, h = bh & 15;
    const int r = lane >> 2, cq = (lane & 3) * 2;

    // Q fragments straight from global, reused for all 32 key tiles
    const size_t qbase = ((size_t)b * TT + qt * 128 + wid * 16) * CC + h * DD;
    uint32_t qf[4][4];
#pragma unroll
    for (int kc = 0; kc < 4; kc++)
#pragma unroll
        for (int e = 0; e < 4; e++) {
            size_t off = qbase + (size_t)(r + (e & 1) * 8) * CC + kc * 16 + cq + (e >> 1) * 8;
            qf[kc][e] = *(const uint32_t*)(g_q + off);
        }

    float oacc[8][4];
#pragma unroll
    for (int nf = 0; nf < 8; nf++)
#pragma unroll
        for (int e = 0; e < 4; e++) oacc[nf][e] = 0.f;
    float m0r = -1e30f, m1r = -1e30f, l0r = 0.f, l1r = 0.f;

    const int grp = lane >> 3, r8 = lane & 7;
    const uint32_t kOff = (uint32_t)((r8 + (grp >> 1) * 8) * RSTR + (grp & 1) * 16);
    const uint32_t vOff = (uint32_t)(((grp & 1) * 8 + r8) * RSTR + (grp >> 1) * 16);
    const size_t kvb = (size_t)b * TT * CC + h * DD;

    auto load_tile = [&](int kt, int st) {
        const uint32_t s0 = smu + st * STG;
        const int t0 = kt * 64;
#pragma unroll
        for (int it = 0; it < 2; it++) {
            int i = it * 256 + tid;
            int rr = i >> 3, c = i & 7;
            uint32_t sa = s0 + rr * RSTR + c * 16;
            cp16(sa,       (const char*)(g_k + kvb + (size_t)(t0 + rr) * CC) + c * 16);
            cp16(sa + BUF, (const char*)(g_v + kvb + (size_t)(t0 + rr) * CC) + c * 16);
        }
        asm volatile("cp.async.commit_group;" ::: "memory");
    };

    load_tile(0, 0);
    load_tile(1, 1);

    int st = 0;
    for (int kt = 0; kt < NT; kt++) {
        if (kt + 2 < NT) { asm volatile("cp.async.wait_group 1;" ::: "memory"); }
        else             { asm volatile("cp.async.wait_group 0;" ::: "memory"); }
        __syncthreads();
        if (kt + 2 < NT) {
            int st2 = st + 2; if (st2 >= NSTG) st2 -= NSTG;
            load_tile(kt + 2, st2);
        }

        const uint32_t sK = smu + st * STG;
        const uint32_t sV = sK + BUF;

        // ---- S = Q K^T (single pass, kk-pairs batched) ----
        float sacc[8][4];
#pragma unroll
        for (int nf = 0; nf < 8; nf++)
#pragma unroll
            for (int e = 0; e < 4; e++) sacc[nf][e] = 0.f;
#pragma unroll
        for (int half = 0; half < 2; half++) {
            uint32_t bF[2][4][4];
#pragma unroll
            for (int k2 = 0; k2 < 2; k2++) {
                const uint32_t kb = (half * 2 + k2) * 32;
#pragma unroll
                for (int nj = 0; nj < 4; nj++)
                    ldm_x4(sK + kOff + nj * 16 * RSTR + kb, bF[k2][nj]);
            }
#pragma unroll
            for (int k2 = 0; k2 < 2; k2++)
#pragma unroll
                for (int nf = 0; nf < 8; nf++)
                    mma16816(sacc[nf], qf[half * 2 + k2], &bF[k2][nf >> 1][(nf & 1) * 2]);
        }

        // ---- online softmax (exp2 domain, MUFU ex2) ----
        float mx0 = -1e30f, mx1 = -1e30f;
#pragma unroll
        for (int nf = 0; nf < 8; nf++) {
            mx0 = fmaxf(mx0, fmaxf(sacc[nf][0], sacc[nf][1]));
            mx1 = fmaxf(mx1, fmaxf(sacc[nf][2], sacc[nf][3]));
        }
        mx0 = fmaxf(mx0, __shfl_xor_sync(0xffffffffu, mx0, 1));
        mx0 = fmaxf(mx0, __shfl_xor_sync(0xffffffffu, mx0, 2));
        mx1 = fmaxf(mx1, __shfl_xor_sync(0xffffffffu, mx1, 1));
        mx1 = fmaxf(mx1, __shfl_xor_sync(0xffffffffu, mx1, 2));
        const float mn0 = fmaxf(m0r, mx0), mn1 = fmaxf(m1r, mx1);
        const float al0 = ex2(m0r - mn0), al1 = ex2(m1r - mn1);
        float ls0 = 0.f, ls1 = 0.f;
#pragma unroll
        for (int nf = 0; nf < 8; nf++) {
            sacc[nf][0] = ex2(sacc[nf][0] - mn0);
            sacc[nf][1] = ex2(sacc[nf][1] - mn0);
            sacc[nf][2] = ex2(sacc[nf][2] - mn1);
            sacc[nf][3] = ex2(sacc[nf][3] - mn1);
            ls0 += sacc[nf][0] + sacc[nf][1];
            ls1 += sacc[nf][2] + sacc[nf][3];
        }
        ls0 += __shfl_xor_sync(0xffffffffu, ls0, 1);
        ls0 += __shfl_xor_sync(0xffffffffu, ls0, 2);
        ls1 += __shfl_xor_sync(0xffffffffu, ls1, 1);
        ls1 += __shfl_xor_sync(0xffffffffu, ls1, 2);
        l0r = l0r * al0 + ls0; m0r = mn0;
        l1r = l1r * al1 + ls1; m1r = mn1;
#pragma unroll
        for (int nf = 0; nf < 8; nf++) {
            oacc[nf][0] *= al0; oacc[nf][1] *= al0;
            oacc[nf][2] *= al1; oacc[nf][3] *= al1;
        }

        // ---- P -> fp16 A-fragments (accumulator layout identity) ----
        uint32_t pf[4][4];
#pragma unroll
        for (int kc = 0; kc < 4; kc++) {
            pf[kc][0] = pack2h(sacc[2 * kc][0],     sacc[2 * kc][1]);
            pf[kc][1] = pack2h(sacc[2 * kc][2],     sacc[2 * kc][3]);
            pf[kc][2] = pack2h(sacc[2 * kc + 1][0], sacc[2 * kc + 1][1]);
            pf[kc][3] = pack2h(sacc[2 * kc + 1][2], sacc[2 * kc + 1][3]);
        }

        // ---- O += P V (single pass, kc-pairs batched), V via ldmatrix.trans ----
#pragma unroll
        for (int half = 0; half < 2; half++) {
            uint32_t vF[2][4][4];
#pragma unroll
            for (int k2 = 0; k2 < 2; k2++) {
                const int kc = half * 2 + k2;
#pragma unroll
                for (int db = 0; db < 4; db++)
                    ldm_x4t(sV + kc * 16 * RSTR + vOff + db * 32, vF[k2][db]);
            }
#pragma unroll
            for (int k2 = 0; k2 < 2; k2++)
#pragma unroll
                for (int nf = 0; nf < 8; nf++)
                    mma16816(oacc[nf], pf[half * 2 + k2], &vF[k2][nf >> 1][(nf & 1) * 2]);
        }
        if (++st == NSTG) st = 0;
    }

    const float inv0 = 1.f / l0r, inv1 = 1.f / l1r;
    const size_t yb = ((size_t)b * TT + qt * 128 + wid * 16) * CC + h * DD;
#pragma unroll
    for (int nf = 0; nf < 8; nf++) {
        const int col = nf * 8 + cq;
        *(uint32_t*)(g_y + yb + (size_t)r * CC + col) =
            pack2h(oacc[nf][0] * inv0, oacc[nf][1] * inv0);
        *(uint32_t*)(g_y + yb + (size_t)(r + 8) * CC + col) =
            pack2h(oacc[nf][2] * inv1, oacc[nf][3] * inv1);
    }
}

// ---------------- host launcher ----------------
extern "C" void kernel_launch(void* const* d_in, const int* in_sizes, int n_in,
                              void* d_out, int out_size) {
    const float* x  = (const float*)d_in[0];
    const float* wa = (const float*)d_in[1];
    const float* wp = (const float*)d_in[2];
    float* out = (float*)d_out;

    constexpr int SM_GEMM  = 3 * 2 * 128 * 80;   // 61440 (3 stages x [A,B])
    constexpr int SM_FLASH = 3 * 2 * 64 * 144;   // 55296 (3 stages x [K,V])

    cudaFuncSetAttribute((const void*)gemm_mma<0>, cudaFuncAttributeMaxDynamicSharedMemorySize, SM_GEMM);
    cudaFuncSetAttribute((const void*)gemm_mma<1>, cudaFuncAttributeMaxDynamicSharedMemorySize, SM_GEMM);
    cudaFuncSetAttribute((const void*)flash_k,     cudaFuncAttributeMaxDynamicSharedMemorySize, SM_FLASH);

    xprep_k<<<MROWS * CC / 1024, 256>>>(x);
    wprep_k<<<dim3(C3 / 32, CC / 32), 256>>>(wa, C3, 1);
    wprep_k<<<dim3(CC / 32, CC / 32), 256>>>(wp, CC, 0);

    gemm_mma<0><<<dim3(C3 / 128, MROWS / 128), 256, SM_GEMM>>>(nullptr);  // qkv (1-pass)
    flash_k<<<dim3(TT / 128, NBH), 256, SM_FLASH>>>();                    // fused attention
    gemm_mma<1><<<dim3(CC / 128, MROWS / 128), 256, SM_GEMM>>>(out);      // proj (1-pass)
}

// round 12
// speedup vs baseline: 15.4829x; 1.0843x over previous
#include <cuda_runtime.h>
#include <cuda_fp16.h>
#include <cstdint>

#define BB 2
#define TT 2048
#define CC 1024
#define HH 16
#define DD 64
#define C3 3072
#define MROWS 4096   // BB*TT
#define NBH 32       // BB*HH

// ---------------- device global scratch ----------------
__device__ __align__(16) __half g_x[MROWS * CC];     // x fp16
__device__ __align__(16) __half g_wa[C3 * CC];       // w_attn^T fp16 (q cols pre-scaled)
__device__ __align__(16) __half g_wp[CC * CC];       // w_proj^T fp16
__device__ __align__(16) __half g_q[MROWS * CC];     // q fp16 [b,t,h*d]
__device__ __align__(16) __half g_k[MROWS * CC];     // k fp16
__device__ __align__(16) __half g_v[MROWS * CC];     // v fp16
__device__ __align__(16) __half g_y[MROWS * CC];     // attn out fp16

// ---------------- helpers ----------------
__device__ __forceinline__ uint32_t smem_u32(const void* p) {
    uint32_t a;
    asm("{ .reg .u64 t; cvta.to.shared.u64 t, %1; cvt.u32.u64 %0, t; }" : "=r"(a) : "l"(p));
    return a;
}
__device__ __forceinline__ void cp16(uint32_t s, const void* g) {
    asm volatile("cp.async.cg.shared.global [%0], [%1], 16;" :: "r"(s), "l"(g));
}
__device__ __forceinline__ void ldm_x4(uint32_t addr, uint32_t* r) {
    asm volatile("ldmatrix.sync.aligned.m8n8.x4.shared.b16 {%0,%1,%2,%3}, [%4];"
                 : "=r"(r[0]), "=r"(r[1]), "=r"(r[2]), "=r"(r[3]) : "r"(addr));
}
__device__ __forceinline__ void ldm_x4t(uint32_t addr, uint32_t* r) {
    asm volatile("ldmatrix.sync.aligned.m8n8.x4.trans.shared.b16 {%0,%1,%2,%3}, [%4];"
                 : "=r"(r[0]), "=r"(r[1]), "=r"(r[2]), "=r"(r[3]) : "r"(addr));
}
__device__ __forceinline__ void mma16816(float* c, const uint32_t* a, const uint32_t* b) {
    asm volatile("mma.sync.aligned.m16n8k16.row.col.f32.f16.f16.f32 "
                 "{%0,%1,%2,%3}, {%4,%5,%6,%7}, {%8,%9}, {%0,%1,%2,%3};"
                 : "+f"(c[0]), "+f"(c[1]), "+f"(c[2]), "+f"(c[3])
                 : "r"(a[0]), "r"(a[1]), "r"(a[2]), "r"(a[3]), "r"(b[0]), "r"(b[1]));
}
__device__ __forceinline__ uint32_t pack2h(float x, float y) {
    __half2 h = __floats2half2_rn(x, y);
    return *(uint32_t*)&h;
}
__device__ __forceinline__ float ex2(float x) {
    float y;
    asm("ex2.approx.ftz.f32 %0, %1;" : "=f"(y) : "f"(x));
    return y;
}

// ---------------- merged prep kernel ----------------
// blocks [0,4096): x fp32->fp16
// blocks [4096,7168): w_attn transpose (3072 cols), q-cols pre-scaled
// blocks [7168,8192): w_proj transpose (1024 cols)
__global__ void __launch_bounds__(256) prep_k(const float* __restrict__ x,
                                              const float* __restrict__ wa,
                                              const float* __restrict__ wp) {
    __shared__ float ts[32][33];
    const int id = blockIdx.x;
    const int tid = threadIdx.x;
    if (id < 4096) {
        size_t i = ((size_t)id * 256 + tid) * 4;
        float4 v = *(const float4*)(x + i);
        __half h[4] = {__float2half_rn(v.x), __float2half_rn(v.y),
                       __float2half_rn(v.z), __float2half_rn(v.w)};
        *(uint2*)(g_x + i) = *(uint2*)h;
        return;
    }
    const int isattn = (id < 7168);
    const int j = isattn ? (id - 4096) : (id - 7168);
    const int NBLK = isattn ? 96 : 32;
    const int N = isattn ? C3 : CC;
    const float* w = isattn ? wa : wp;
    __half* t = isattn ? g_wa : g_wp;
    const int n0 = (j % NBLK) * 32, c0 = (j / NBLK) * 32;
    const int tx = tid & 31, ty = tid >> 5;
#pragma unroll
    for (int jj = 0; jj < 4; jj++)
        ts[ty + jj * 8][tx] = w[(size_t)(c0 + ty + jj * 8) * N + n0 + tx];
    __syncthreads();
#pragma unroll
    for (int jj = 0; jj < 4; jj++) {
        int n = n0 + ty + jj * 8;
        float v = ts[tx][ty + jj * 8];
        if (isattn && n < CC) v *= 0.18033688011112042f;  // (1/sqrt 64)*log2(e)
        t[(size_t)n * CC + c0 + tx] = __float2half_rn(v);
    }
}

// ---------------- mma.sync GEMM (1-pass fp16, batched fragment loads) ----------------
// MODE 0: qkv = x * w_attn^T  -> g_q/g_k/g_v fp16   (per-half: M=2048, N=3072)
// MODE 1: out = y * w_proj^T  -> fp32 out           (per-half: M=2048, N=1024)
template<int MODE>
__global__ void __launch_bounds__(256, 2) gemm_mma(float* __restrict__ outp, int moff) {
    constexpr int NTILE = 128;
    constexpr int NC  = 32;           // k chunks of 32
    constexpr int LDA = CC, LDB = CC;
    constexpr int WN  = NTILE / 2;
    constexpr int NN8 = WN / 8;
    constexpr int NJ  = WN / 16;
    constexpr int ASZ = 128 * 80;     // one 128x32 fp16 tile, 80B rows
    constexpr int STG = 2 * ASZ;      // [A,B]
    constexpr int NSTG = 3;

    extern __shared__ char sm[];
    const uint32_t smu = smem_u32(sm);
    const int tid = threadIdx.x, lane = tid & 31, wid = tid >> 5;
    const int wm = wid & 3, wn = wid >> 2;
    const int warpM = wm * 32, warpN = wn * WN;
    const int nt = blockIdx.x, mt = blockIdx.y + moff;
    const int m0 = mt * 128, n0 = nt * NTILE;

    const __half *a_p, *b_p;
    if constexpr (MODE == 0) {
        a_p = g_x + (size_t)m0 * CC;
        b_p = g_wa + (size_t)n0 * CC;
    } else {
        a_p = g_y + (size_t)m0 * CC;
        b_p = g_wp + (size_t)n0 * CC;
    }

    auto load_stage = [&](int st, int kc) {
        const uint32_t s0 = smu + st * STG;
        const int k0 = kc * 32;
#pragma unroll
        for (int i0 = 0; i0 < 128 * 4; i0 += 256) {
            int i = i0 + tid, r = i >> 2, c = i & 3;
            uint32_t sa = s0 + r * 80 + c * 16;
            cp16(sa,       (const char*)(a_p + (size_t)r * LDA + k0) + c * 16);
            cp16(sa + ASZ, (const char*)(b_p + (size_t)r * LDB + k0) + c * 16);
        }
        asm volatile("cp.async.commit_group;" ::: "memory");
    };

    const int grp = lane >> 3, r8 = lane & 7;
    const uint32_t aOff = (uint32_t)((warpM + r8 + (grp & 1) * 8) * 80 + (grp >> 1) * 16);
    const uint32_t bOff = (uint32_t)((warpN + r8 + (grp >> 1) * 8) * 80 + (grp & 1) * 16);

    float acc[2][NN8][4];
#pragma unroll
    for (int mi = 0; mi < 2; mi++)
#pragma unroll
        for (int ni = 0; ni < NN8; ni++)
#pragma unroll
            for (int e = 0; e < 4; e++) acc[mi][ni][e] = 0.f;

    load_stage(0, 0);
    load_stage(1, 1);

    int st = 0;
    for (int c = 0; c < NC; c++) {
        if (c + 2 < NC) { asm volatile("cp.async.wait_group 1;" ::: "memory"); }
        else            { asm volatile("cp.async.wait_group 0;" ::: "memory"); }
        __syncthreads();
        if (c + 2 < NC) {
            int st2 = st + 2; if (st2 >= NSTG) st2 -= NSTG;
            load_stage(st2, c + 2);
        }

        const uint32_t sA = smu + st * STG;
        const uint32_t sB = sA + ASZ;
        uint32_t aF[2][2][4], bF[2][NJ][4];
#pragma unroll
        for (int kk = 0; kk < 2; kk++) {
            const uint32_t kb = kk * 32;
            ldm_x4(sA + aOff + kb,           aF[kk][0]);
            ldm_x4(sA + aOff + 16 * 80 + kb, aF[kk][1]);
#pragma unroll
            for (int nj = 0; nj < NJ; nj++)
                ldm_x4(sB + bOff + nj * 16 * 80 + kb, bF[kk][nj]);
        }
#pragma unroll
        for (int kk = 0; kk < 2; kk++)
#pragma unroll
            for (int mi = 0; mi < 2; mi++)
#pragma unroll
                for (int ni = 0; ni < NN8; ni++)
                    mma16816(acc[mi][ni], aF[kk][mi], &bF[kk][ni >> 1][(ni & 1) * 2]);
        if (++st == NSTG) st = 0;
    }

    const int row_l = lane >> 2, col_l = (lane & 3) * 2;
#pragma unroll
    for (int mi = 0; mi < 2; mi++) {
#pragma unroll
        for (int ni = 0; ni < NN8; ni++) {
            const int gr0 = m0 + warpM + mi * 16 + row_l;
            const int gc  = n0 + warpN + ni * 8 + col_l;
            const float* cc = acc[mi][ni];
            if constexpr (MODE == 0) {
                __half* dst;
                int gcl;
                if (gc < CC)           { dst = g_q; gcl = gc; }
                else if (gc < 2 * CC)  { dst = g_k; gcl = gc - CC; }
                else                   { dst = g_v; gcl = gc - 2 * CC; }
                *(uint32_t*)(dst + (size_t)gr0 * CC + gcl)       = pack2h(cc[0], cc[1]);
                *(uint32_t*)(dst + (size_t)(gr0 + 8) * CC + gcl) = pack2h(cc[2], cc[3]);
            } else {
                *(float2*)(outp + (size_t)gr0 * CC + gc)       = make_float2(cc[0], cc[1]);
                *(float2*)(outp + (size_t)(gr0 + 8) * CC + gc) = make_float2(cc[2], cc[3]);
            }
        }
    }
}

// ---------------- fused flash attention (fp16 single-pass, log2 domain) ----------------
__global__ void __launch_bounds__(256) flash_k(int bhoff) {
    constexpr int RSTR = 144;
    constexpr int BUF  = 64 * RSTR;   // one 64x64 fp16 tile
    constexpr int STG  = 2 * BUF;     // K, V
    constexpr int NSTG = 3;
    constexpr int NT   = TT / 64;

    extern __shared__ char sm[];
    const uint32_t smu = smem_u32(sm);
    const int tid = threadIdx.x, lane = tid & 31, wid = tid >> 5;
    const int qt = blockIdx.x, bh = blockIdx.y + bhoff;
    const int b = bh >> 4, h = bh & 15;
    const int r = lane >> 2, cq = (lane & 3) * 2;

    const size_t qbase = ((size_t)b * TT + qt * 128 + wid * 16) * CC + h * DD;
    uint32_t qf[4][4];
#pragma unroll
    for (int kc = 0; kc < 4; kc++)
#pragma unroll
        for (int e = 0; e < 4; e++) {
            size_t off = qbase + (size_t)(r + (e & 1) * 8) * CC + kc * 16 + cq + (e >> 1) * 8;
            qf[kc][e] = *(const uint32_t*)(g_q + off);
        }

    float oacc[8][4];
#pragma unroll
    for (int nf = 0; nf < 8; nf++)
#pragma unroll
        for (int e = 0; e < 4; e++) oacc[nf][e] = 0.f;
    float m0r = -1e30f, m1r = -1e30f, l0r = 0.f, l1r = 0.f;

    const int grp = lane >> 3, r8 = lane & 7;
    const uint32_t kOff = (uint32_t)((r8 + (grp >> 1) * 8) * RSTR + (grp & 1) * 16);
    const uint32_t vOff = (uint32_t)(((grp & 1) * 8 + r8) * RSTR + (grp >> 1) * 16);
    const size_t kvb = (size_t)b * TT * CC + h * DD;

    auto load_tile = [&](int kt, int st) {
        const uint32_t s0 = smu + st * STG;
        const int t0 = kt * 64;
#pragma unroll
        for (int it = 0; it < 2; it++) {
            int i = it * 256 + tid;
            int rr = i >> 3, c = i & 7;
            uint32_t sa = s0 + rr * RSTR + c * 16;
            cp16(sa,       (const char*)(g_k + kvb + (size_t)(t0 + rr) * CC) + c * 16);
            cp16(sa + BUF, (const char*)(g_v + kvb + (size_t)(t0 + rr) * CC) + c * 16);
        }
        asm volatile("cp.async.commit_group;" ::: "memory");
    };

    load_tile(0, 0);
    load_tile(1, 1);

    int st = 0;
    for (int kt = 0; kt < NT; kt++) {
        if (kt + 2 < NT) { asm volatile("cp.async.wait_group 1;" ::: "memory"); }
        else             { asm volatile("cp.async.wait_group 0;" ::: "memory"); }
        __syncthreads();
        if (kt + 2 < NT) {
            int st2 = st + 2; if (st2 >= NSTG) st2 -= NSTG;
            load_tile(kt + 2, st2);
        }

        const uint32_t sK = smu + st * STG;
        const uint32_t sV = sK + BUF;

        // ---- S = Q K^T (single pass, kk-pairs batched) ----
        float sacc[8][4];
#pragma unroll
        for (int nf = 0; nf < 8; nf++)
#pragma unroll
            for (int e = 0; e < 4; e++) sacc[nf][e] = 0.f;
#pragma unroll
        for (int half = 0; half < 2; half++) {
            uint32_t bF[2][4][4];
#pragma unroll
            for (int k2 = 0; k2 < 2; k2++) {
                const uint32_t kb = (half * 2 + k2) * 32;
#pragma unroll
                for (int nj = 0; nj < 4; nj++)
                    ldm_x4(sK + kOff + nj * 16 * RSTR + kb, bF[k2][nj]);
            }
#pragma unroll
            for (int k2 = 0; k2 < 2; k2++)
#pragma unroll
                for (int nf = 0; nf < 8; nf++)
                    mma16816(sacc[nf], qf[half * 2 + k2], &bF[k2][nf >> 1][(nf & 1) * 2]);
        }

        // ---- online softmax (exp2 domain, MUFU ex2) ----
        float mx0 = -1e30f, mx1 = -1e30f;
#pragma unroll
        for (int nf = 0; nf < 8; nf++) {
            mx0 = fmaxf(mx0, fmaxf(sacc[nf][0], sacc[nf][1]));
            mx1 = fmaxf(mx1, fmaxf(sacc[nf][2], sacc[nf][3]));
        }
        mx0 = fmaxf(mx0, __shfl_xor_sync(0xffffffffu, mx0, 1));
        mx0 = fmaxf(mx0, __shfl_xor_sync(0xffffffffu, mx0, 2));
        mx1 = fmaxf(mx1, __shfl_xor_sync(0xffffffffu, mx1, 1));
        mx1 = fmaxf(mx1, __shfl_xor_sync(0xffffffffu, mx1, 2));
        const float mn0 = fmaxf(m0r, mx0), mn1 = fmaxf(m1r, mx1);
        const float al0 = ex2(m0r - mn0), al1 = ex2(m1r - mn1);
        float ls0 = 0.f, ls1 = 0.f;
#pragma unroll
        for (int nf = 0; nf < 8; nf++) {
            sacc[nf][0] = ex2(sacc[nf][0] - mn0);
            sacc[nf][1] = ex2(sacc[nf][1] - mn0);
            sacc[nf][2] = ex2(sacc[nf][2] - mn1);
            sacc[nf][3] = ex2(sacc[nf][3] - mn1);
            ls0 += sacc[nf][0] + sacc[nf][1];
            ls1 += sacc[nf][2] + sacc[nf][3];
        }
        ls0 += __shfl_xor_sync(0xffffffffu, ls0, 1);
        ls0 += __shfl_xor_sync(0xffffffffu, ls0, 2);
        ls1 += __shfl_xor_sync(0xffffffffu, ls1, 1);
        ls1 += __shfl_xor_sync(0xffffffffu, ls1, 2);
        l0r = l0r * al0 + ls0; m0r = mn0;
        l1r = l1r * al1 + ls1; m1r = mn1;
#pragma unroll
        for (int nf = 0; nf < 8; nf++) {
            oacc[nf][0] *= al0; oacc[nf][1] *= al0;
            oacc[nf][2] *= al1; oacc[nf][3] *= al1;
        }

        // ---- P -> fp16 A-fragments ----
        uint32_t pf[4][4];
#pragma unroll
        for (int kc = 0; kc < 4; kc++) {
            pf[kc][0] = pack2h(sacc[2 * kc][0],     sacc[2 * kc][1]);
            pf[kc][1] = pack2h(sacc[2 * kc][2],     sacc[2 * kc][3]);
            pf[kc][2] = pack2h(sacc[2 * kc + 1][0], sacc[2 * kc + 1][1]);
            pf[kc][3] = pack2h(sacc[2 * kc + 1][2], sacc[2 * kc + 1][3]);
        }

        // ---- O += P V (single pass, kc-pairs batched), V via ldmatrix.trans ----
#pragma unroll
        for (int half = 0; half < 2; half++) {
            uint32_t vF[2][4][4];
#pragma unroll
            for (int k2 = 0; k2 < 2; k2++) {
                const int kc = half * 2 + k2;
#pragma unroll
                for (int db = 0; db < 4; db++)
                    ldm_x4t(sV + kc * 16 * RSTR + vOff + db * 32, vF[k2][db]);
            }
#pragma unroll
            for (int k2 = 0; k2 < 2; k2++)
#pragma unroll
                for (int nf = 0; nf < 8; nf++)
                    mma16816(oacc[nf], pf[half * 2 + k2], &vF[k2][nf >> 1][(nf & 1) * 2]);
        }
        if (++st == NSTG) st = 0;
    }

    const float inv0 = 1.f / l0r, inv1 = 1.f / l1r;
    const size_t yb = ((size_t)b * TT + qt * 128 + wid * 16) * CC + h * DD;
#pragma unroll
    for (int nf = 0; nf < 8; nf++) {
        const int col = nf * 8 + cq;
        *(uint32_t*)(g_y + yb + (size_t)r * CC + col) =
            pack2h(oacc[nf][0] * inv0, oacc[nf][1] * inv0);
        *(uint32_t*)(g_y + yb + (size_t)(r + 8) * CC + col) =
            pack2h(oacc[nf][2] * inv1, oacc[nf][3] * inv1);
    }
}

// ---------------- host launcher: per-batch chains on forked streams ----------------
extern "C" void kernel_launch(void* const* d_in, const int* in_sizes, int n_in,
                              void* d_out, int out_size) {
    const float* x  = (const float*)d_in[0];
    const float* wa = (const float*)d_in[1];
    const float* wp = (const float*)d_in[2];
    float* out = (float*)d_out;

    constexpr int SM_GEMM  = 3 * 2 * 128 * 80;   // 61440
    constexpr int SM_FLASH = 3 * 2 * 64 * 144;   // 55296

    // one-time init on the (non-captured) correctness call
    static cudaStream_t s2 = nullptr;
    static cudaEvent_t e_fork = nullptr, e_join = nullptr;
    if (!s2) {
        cudaStreamCreateWithFlags(&s2, cudaStreamNonBlocking);
        cudaEventCreateWithFlags(&e_fork, cudaEventDisableTiming);
        cudaEventCreateWithFlags(&e_join, cudaEventDisableTiming);
        cudaFuncSetAttribute((const void*)gemm_mma<0>, cudaFuncAttributeMaxDynamicSharedMemorySize, SM_GEMM);
        cudaFuncSetAttribute((const void*)gemm_mma<1>, cudaFuncAttributeMaxDynamicSharedMemorySize, SM_GEMM);
        cudaFuncSetAttribute((const void*)flash_k,     cudaFuncAttributeMaxDynamicSharedMemorySize, SM_FLASH);
    }

    // merged prep (x convert + both weight transposes)
    prep_k<<<8192, 256>>>(x, wa, wp);

    // fork: batch-1 chain depends on prep only
    cudaEventRecord(e_fork, 0);
    cudaStreamWaitEvent(s2, e_fork, 0);

    // batch 0 chain (default stream)
    gemm_mma<0><<<dim3(C3 / 128, 16), 256, SM_GEMM>>>(nullptr, 0);
    flash_k<<<dim3(TT / 128, 16), 256, SM_FLASH>>>(0);
    gemm_mma<1><<<dim3(CC / 128, 16), 256, SM_GEMM>>>(out, 0);

    // batch 1 chain (s2, non-blocking -> concurrent with default stream)
    gemm_mma<0><<<dim3(C3 / 128, 16), 256, SM_GEMM, s2>>>(nullptr, 16);
    flash_k<<<dim3(TT / 128, 16), 256, SM_FLASH, s2>>>(16);
    gemm_mma<1><<<dim3(CC / 128, 16), 256, SM_GEMM, s2>>>(out, 16);

    // join
    cudaEventRecord(e_join, s2);
    cudaStreamWaitEvent(0, e_join, 0);
}